// round 1
// baseline (speedup 1.0000x reference)
#include <cuda_runtime.h>
#include <math.h>

// ---------------- problem constants ----------------
#define B_   2
#define S_   2048
#define D_   1024
#define HQ_  16
#define HKV_ 4
#define HD_  64
#define P_   4096
#define M_   (B_ * S_)        // 4096 rows (b,s)
#define KVD_ (HKV_ * HD_)     // 256

// ---------------- scratch (static device globals; no allocs allowed) -----
__device__ float g_h [M_ * D_];    // ln1 out; reused for ln2 out
__device__ float g_q [M_ * D_];
__device__ float g_k [M_ * KVD_];
__device__ float g_v [M_ * KVD_];
__device__ float g_o [M_ * D_];    // attention output (pre-wo)
__device__ float g_x2[M_ * D_];    // x + o@wo
__device__ float g_mid[M_ * P_];   // gelu(h2@w1+b1)

// ---------------- LayerNorm: one block per row (D=1024, 256 thr) ---------
__global__ __launch_bounds__(256) void ln_kernel(
    const float* __restrict__ x, const float* __restrict__ gam,
    const float* __restrict__ bet, float* __restrict__ out)
{
    __shared__ float red[20];
    int row = blockIdx.x;
    int tid = threadIdx.x;
    const float* xr = x + (size_t)row * D_;
    float4 v = *(const float4*)&xr[tid * 4];
    float s  = v.x + v.y + v.z + v.w;
    float sq = v.x * v.x + v.y * v.y + v.z * v.z + v.w * v.w;
    #pragma unroll
    for (int o = 16; o; o >>= 1) {
        s  += __shfl_xor_sync(0xffffffffu, s,  o);
        sq += __shfl_xor_sync(0xffffffffu, sq, o);
    }
    if ((tid & 31) == 0) { red[tid >> 5] = s; red[8 + (tid >> 5)] = sq; }
    __syncthreads();
    if (tid < 32) {
        float a = (tid < 8) ? red[tid]     : 0.f;
        float b = (tid < 8) ? red[8 + tid] : 0.f;
        #pragma unroll
        for (int o = 4; o; o >>= 1) {
            a += __shfl_xor_sync(0xffffffffu, a, o);
            b += __shfl_xor_sync(0xffffffffu, b, o);
        }
        if (tid == 0) { red[16] = a; red[17] = b; }
    }
    __syncthreads();
    float mean = red[16] * (1.f / D_);
    float var  = red[17] * (1.f / D_) - mean * mean;
    float rs   = rsqrtf(var + 1e-5f);
    float4 gv = *(const float4*)&gam[tid * 4];
    float4 bv = *(const float4*)&bet[tid * 4];
    float4 ov;
    ov.x = (v.x - mean) * rs * gv.x + bv.x;
    ov.y = (v.y - mean) * rs * gv.y + bv.y;
    ov.z = (v.z - mean) * rs * gv.z + bv.z;
    ov.w = (v.w - mean) * rs * gv.w + bv.w;
    *(float4*)&out[(size_t)row * D_ + tid * 4] = ov;
}

// ---------------- RoPE (in place), grid (M_, nheads), 32 threads --------
__global__ void rope_kernel(float* __restrict__ buf, int nheads)
{
    int t = blockIdx.x;          // row index (b*S + s)
    int h = blockIdx.y;
    int j = threadIdx.x;         // 0..31 (pair index)
    int s = t & (S_ - 1);        // s = t % S_
    float inv = 1.0f / powf(10000.0f, (float)(2 * j) / 64.0f);
    float ang = (float)s * inv;
    float sn, c;
    sincosf(ang, &sn, &c);
    float* p = buf + (size_t)t * (nheads * HD_) + h * HD_;
    float x1 = p[j], x2 = p[j + 32];
    p[j]      = x1 * c - x2 * sn;
    p[j + 32] = x1 * sn + x2 * c;
}

// ---------------- fp32 tiled GEMM: C = A[MxK] @ B[KxN] (+epilogue) ------
#define GBM 128
#define GBN 128
#define GBK 16

enum { EPI_NONE = 0, EPI_RES = 1, EPI_BIAS_GELU = 2, EPI_BIAS_RES = 3 };

template <int EPI>
__global__ __launch_bounds__(256) void gemm_kernel(
    const float* __restrict__ A, const float* __restrict__ Bm,
    const float* __restrict__ bias, const float* __restrict__ res,
    float* __restrict__ C, int M, int N, int K)
{
    __shared__ float As[GBK][GBM + 4];   // stride 132 (16B-aligned rows)
    __shared__ float Bs[GBK][GBN + 4];
    int tid = threadIdx.x;
    int tx = tid & 15, ty = tid >> 4;
    int m0 = blockIdx.y * GBM, n0 = blockIdx.x * GBN;

    float acc[8][8] = {};
    int arow = tid >> 2, acol = (tid & 3) << 2;    // A tile: 128 rows x 16 k
    int brow = tid >> 5, bcol = (tid & 31) << 2;   // B tile: 16 k x 128 cols

    for (int k0 = 0; k0 < K; k0 += GBK) {
        #pragma unroll
        for (int r = 0; r < 2; r++) {
            float4 av = *(const float4*)&A[(size_t)(m0 + arow + 64 * r) * K + k0 + acol];
            As[acol + 0][arow + 64 * r] = av.x;
            As[acol + 1][arow + 64 * r] = av.y;
            As[acol + 2][arow + 64 * r] = av.z;
            As[acol + 3][arow + 64 * r] = av.w;
            float4 bv = *(const float4*)&Bm[(size_t)(k0 + brow + 8 * r) * N + n0 + bcol];
            *(float4*)&Bs[brow + 8 * r][bcol] = bv;
        }
        __syncthreads();
        #pragma unroll
        for (int k = 0; k < GBK; k++) {
            float a[8], b[8];
            *(float4*)&a[0] = *(float4*)&As[k][ty * 8];
            *(float4*)&a[4] = *(float4*)&As[k][ty * 8 + 4];
            *(float4*)&b[0] = *(float4*)&Bs[k][tx * 8];
            *(float4*)&b[4] = *(float4*)&Bs[k][tx * 8 + 4];
            #pragma unroll
            for (int i = 0; i < 8; i++)
                #pragma unroll
                for (int j = 0; j < 8; j++)
                    acc[i][j] += a[i] * b[j];
        }
        __syncthreads();
    }

    #pragma unroll
    for (int i = 0; i < 8; i++) {
        int m = m0 + ty * 8 + i;
        #pragma unroll
        for (int j = 0; j < 8; j++) {
            int n = n0 + tx * 8 + j;
            size_t idx = (size_t)m * N + n;
            float v = acc[i][j];
            if (EPI == EPI_RES) v += res[idx];
            if (EPI == EPI_BIAS_GELU) {
                float u = v + bias[n];
                v = 0.5f * u * (1.f + tanhf(0.7978845608028654f * (u + 0.044715f * u * u * u)));
            }
            if (EPI == EPI_BIAS_RES) v = v + bias[n] + res[idx];
            C[idx] = v;
        }
    }
}

// ---------------- causal flash attention ---------------------------------
// grid (S_/AQ, HQ_, B_), 256 threads. Tiles: 64 q-rows x 32 kv-cols.
#define AQ 64
#define AC 32

__global__ __launch_bounds__(256) void attn_kernel(
    const float* __restrict__ Q, const float* __restrict__ Kg,
    const float* __restrict__ Vg, float* __restrict__ O)
{
    __shared__ float Qs[AQ][HD_ + 1];
    __shared__ float Ks[AC][HD_ + 1];
    __shared__ float Vs[AC][HD_ + 1];
    __shared__ float Ss[AQ][AC + 1];
    __shared__ float mrow[AQ], lrow[AQ], crow[AQ];

    int tid = threadIdx.x;
    int tx = tid & 15, ty = tid >> 4;
    int qt = blockIdx.x, hq = blockIdx.y, b = blockIdx.z;
    int q0 = qt * AQ;
    int kvh = hq & (HKV_ - 1);                 // kv head = hq % HKV (per reference reshape)
    size_t qbase = ((size_t)(b * S_ + q0)) * D_ + hq * HD_;

    // load Q tile (64 x 64)
    #pragma unroll
    for (int r = 0; r < 4; r++) {
        int row = (tid >> 4) + r * 16;
        int c4  = (tid & 15) * 4;
        float4 v = *(const float4*)&Q[qbase + (size_t)row * D_ + c4];
        Qs[row][c4] = v.x; Qs[row][c4 + 1] = v.y; Qs[row][c4 + 2] = v.z; Qs[row][c4 + 3] = v.w;
    }
    if (tid < AQ) { mrow[tid] = -3.0e38f; lrow[tid] = 0.f; }
    float oacc[4][4] = {};
    __syncthreads();

    int ntiles = (q0 + AQ) / AC;               // = 2*qt + 2 (causal bound)
    for (int t = 0; t < ntiles; t++) {
        int kv0 = t * AC;
        // load K,V tiles (32 x 64)
        #pragma unroll
        for (int r = 0; r < 2; r++) {
            int row = (tid >> 4) + r * 16;
            int c4  = (tid & 15) * 4;
            size_t gidx = ((size_t)(b * S_ + kv0 + row)) * KVD_ + kvh * HD_ + c4;
            float4 kvl = *(const float4*)&Kg[gidx];
            Ks[row][c4] = kvl.x; Ks[row][c4 + 1] = kvl.y; Ks[row][c4 + 2] = kvl.z; Ks[row][c4 + 3] = kvl.w;
            float4 vvl = *(const float4*)&Vg[gidx];
            Vs[row][c4] = vvl.x; Vs[row][c4 + 1] = vvl.y; Vs[row][c4 + 2] = vvl.z; Vs[row][c4 + 3] = vvl.w;
        }
        __syncthreads();

        // scores: 64x32 tile; each thread 4 rows x 2 cols
        float sacc[4][2] = {};
        #pragma unroll 8
        for (int k = 0; k < HD_; k++) {
            float a0 = Qs[ty * 4 + 0][k];
            float a1 = Qs[ty * 4 + 1][k];
            float a2 = Qs[ty * 4 + 2][k];
            float a3 = Qs[ty * 4 + 3][k];
            float b0 = Ks[tx * 2 + 0][k];
            float b1 = Ks[tx * 2 + 1][k];
            sacc[0][0] += a0 * b0; sacc[0][1] += a0 * b1;
            sacc[1][0] += a1 * b0; sacc[1][1] += a1 * b1;
            sacc[2][0] += a2 * b0; sacc[2][1] += a2 * b1;
            sacc[3][0] += a3 * b0; sacc[3][1] += a3 * b1;
        }
        #pragma unroll
        for (int i = 0; i < 4; i++)
            #pragma unroll
            for (int j = 0; j < 2; j++) {
                int r = ty * 4 + i, c = tx * 2 + j;
                int qg = q0 + r, kg = kv0 + c;
                Ss[r][c] = sacc[i][j] * 0.125f + (kg <= qg ? 0.f : -1e9f);
            }
        __syncthreads();

        // online softmax per row (64 rows handled by tid<64)
        if (tid < AQ) {
            int r = tid;
            float mo = mrow[r];
            float tm = mo;
            #pragma unroll 8
            for (int c = 0; c < AC; c++) tm = fmaxf(tm, Ss[r][c]);
            float corr = expf(mo - tm);
            float ps = 0.f;
            #pragma unroll 8
            for (int c = 0; c < AC; c++) {
                float p = expf(Ss[r][c] - tm);
                Ss[r][c] = p;
                ps += p;
            }
            lrow[r] = lrow[r] * corr + ps;
            mrow[r] = tm;
            crow[r] = corr;
        }
        __syncthreads();

        // O = O*corr + P@V ; each thread 4 rows x 4 cols (HD=64)
        #pragma unroll
        for (int i = 0; i < 4; i++) {
            float cf = crow[ty * 4 + i];
            #pragma unroll
            for (int j = 0; j < 4; j++) oacc[i][j] *= cf;
        }
        #pragma unroll 8
        for (int k = 0; k < AC; k++) {
            float p0 = Ss[ty * 4 + 0][k];
            float p1 = Ss[ty * 4 + 1][k];
            float p2 = Ss[ty * 4 + 2][k];
            float p3 = Ss[ty * 4 + 3][k];
            float v0 = Vs[k][tx * 4 + 0];
            float v1 = Vs[k][tx * 4 + 1];
            float v2 = Vs[k][tx * 4 + 2];
            float v3 = Vs[k][tx * 4 + 3];
            oacc[0][0] += p0 * v0; oacc[0][1] += p0 * v1; oacc[0][2] += p0 * v2; oacc[0][3] += p0 * v3;
            oacc[1][0] += p1 * v0; oacc[1][1] += p1 * v1; oacc[1][2] += p1 * v2; oacc[1][3] += p1 * v3;
            oacc[2][0] += p2 * v0; oacc[2][1] += p2 * v1; oacc[2][2] += p2 * v2; oacc[2][3] += p2 * v3;
            oacc[3][0] += p3 * v0; oacc[3][1] += p3 * v1; oacc[3][2] += p3 * v2; oacc[3][3] += p3 * v3;
        }
        __syncthreads();
    }

    // write O (normalized)
    #pragma unroll
    for (int i = 0; i < 4; i++) {
        int r = ty * 4 + i;
        float inv_l = 1.f / lrow[r];
        float4 ov;
        ov.x = oacc[i][0] * inv_l;
        ov.y = oacc[i][1] * inv_l;
        ov.z = oacc[i][2] * inv_l;
        ov.w = oacc[i][3] * inv_l;
        *(float4*)&O[((size_t)(b * S_ + q0 + r)) * D_ + hq * HD_ + tx * 4] = ov;
    }
}

// ---------------- launch ----------------
extern "C" void kernel_launch(void* const* d_in, const int* in_sizes, int n_in,
                              void* d_out, int out_size)
{
    const float* x    = (const float*)d_in[0];
    // d_in[1] = attention_mask (pure causal tril; applied analytically in attn_kernel)
    const float* wq   = (const float*)d_in[2];
    const float* wk   = (const float*)d_in[3];
    const float* wv   = (const float*)d_in[4];
    const float* wo   = (const float*)d_in[5];
    const float* ln1g = (const float*)d_in[6];
    const float* ln1b = (const float*)d_in[7];
    const float* ln2g = (const float*)d_in[8];
    const float* ln2b = (const float*)d_in[9];
    const float* w1   = (const float*)d_in[10];
    const float* b1   = (const float*)d_in[11];
    const float* w2   = (const float*)d_in[12];
    const float* b2   = (const float*)d_in[13];
    float* out = (float*)d_out;

    float *h, *q, *k, *v, *o, *x2, *mid;
    cudaGetSymbolAddress((void**)&h,   g_h);
    cudaGetSymbolAddress((void**)&q,   g_q);
    cudaGetSymbolAddress((void**)&k,   g_k);
    cudaGetSymbolAddress((void**)&v,   g_v);
    cudaGetSymbolAddress((void**)&o,   g_o);
    cudaGetSymbolAddress((void**)&x2,  g_x2);
    cudaGetSymbolAddress((void**)&mid, g_mid);

    // 1. h = LN1(x)
    ln_kernel<<<M_, 256>>>(x, ln1g, ln1b, h);
    // 2-4. q/k/v projections
    gemm_kernel<EPI_NONE><<<dim3(D_ / GBN,  M_ / GBM), 256>>>(h, wq, nullptr, nullptr, q,  M_, D_,  D_);
    gemm_kernel<EPI_NONE><<<dim3(KVD_ / GBN, M_ / GBM), 256>>>(h, wk, nullptr, nullptr, k, M_, KVD_, D_);
    gemm_kernel<EPI_NONE><<<dim3(KVD_ / GBN, M_ / GBM), 256>>>(h, wv, nullptr, nullptr, v, M_, KVD_, D_);
    // 5-6. RoPE
    rope_kernel<<<dim3(M_, HQ_),  32>>>(q, HQ_);
    rope_kernel<<<dim3(M_, HKV_), 32>>>(k, HKV_);
    // 7. attention
    attn_kernel<<<dim3(S_ / AQ, HQ_, B_), 256>>>(q, k, v, o);
    // 8. x2 = x + o @ wo
    gemm_kernel<EPI_RES><<<dim3(D_ / GBN, M_ / GBM), 256>>>(o, wo, nullptr, x, x2, M_, D_, D_);
    // 9. h2 = LN2(x2)   (reuse g_h)
    ln_kernel<<<M_, 256>>>(x2, ln2g, ln2b, h);
    // 10. mid = gelu(h2 @ w1 + b1)
    gemm_kernel<EPI_BIAS_GELU><<<dim3(P_ / GBN, M_ / GBM), 256>>>(h, w1, b1, nullptr, mid, M_, P_, D_);
    // 11. out = x2 + mid @ w2 + b2
    gemm_kernel<EPI_BIAS_RES><<<dim3(D_ / GBN, M_ / GBM), 256>>>(mid, w2, b2, x2, out, M_, D_, P_);
}

// round 4
// speedup vs baseline: 1.6910x; 1.6910x over previous
#include <cuda_runtime.h>
#include <math.h>
#include <stdint.h>

// ---------------- problem constants ----------------
#define B_   2
#define S_   2048
#define D_   1024
#define HQ_  16
#define HKV_ 4
#define HD_  64
#define P_   4096
#define M_   (B_ * S_)        // 4096
#define KVD_ (HKV_ * HD_)     // 256

// ---------------- scratch ----------------
__device__ float g_h [M_ * D_];
__device__ float g_q [M_ * D_];
__device__ float g_k [M_ * KVD_];
__device__ float g_v [M_ * KVD_];
__device__ float g_o [M_ * D_];
__device__ float g_x2[M_ * D_];
__device__ float g_mid[M_ * P_];

__device__ __forceinline__ float to_tf32(float x) {
    float r; asm("cvt.rna.tf32.f32 %0, %1;" : "=f"(r) : "f"(x)); return r;
}

__device__ __forceinline__ void mma_tf32_16n8k8(
    float& d0, float& d1, float& d2, float& d3,
    uint32_t a0, uint32_t a1, uint32_t a2, uint32_t a3,
    uint32_t b0, uint32_t b1)
{
    asm volatile(
        "mma.sync.aligned.m16n8k8.row.col.f32.tf32.tf32.f32 "
        "{%0,%1,%2,%3}, {%4,%5,%6,%7}, {%8,%9}, {%0,%1,%2,%3};"
        : "+f"(d0), "+f"(d1), "+f"(d2), "+f"(d3)
        : "r"(a0), "r"(a1), "r"(a2), "r"(a3), "r"(b0), "r"(b1));
}

// ---------------- LayerNorm ----------------
__global__ __launch_bounds__(256) void ln_kernel(
    const float* __restrict__ x, const float* __restrict__ gam,
    const float* __restrict__ bet, float* __restrict__ out)
{
    __shared__ float red[20];
    int row = blockIdx.x;
    int tid = threadIdx.x;
    const float* xr = x + (size_t)row * D_;
    float4 v = *(const float4*)&xr[tid * 4];
    float s  = v.x + v.y + v.z + v.w;
    float sq = v.x * v.x + v.y * v.y + v.z * v.z + v.w * v.w;
    #pragma unroll
    for (int o = 16; o; o >>= 1) {
        s  += __shfl_xor_sync(0xffffffffu, s,  o);
        sq += __shfl_xor_sync(0xffffffffu, sq, o);
    }
    if ((tid & 31) == 0) { red[tid >> 5] = s; red[8 + (tid >> 5)] = sq; }
    __syncthreads();
    if (tid < 32) {
        float a = (tid < 8) ? red[tid]     : 0.f;
        float b = (tid < 8) ? red[8 + tid] : 0.f;
        #pragma unroll
        for (int o = 4; o; o >>= 1) {
            a += __shfl_xor_sync(0xffffffffu, a, o);
            b += __shfl_xor_sync(0xffffffffu, b, o);
        }
        if (tid == 0) { red[16] = a; red[17] = b; }
    }
    __syncthreads();
    float mean = red[16] * (1.f / D_);
    float var  = red[17] * (1.f / D_) - mean * mean;
    float rs   = rsqrtf(var + 1e-5f);
    float4 gv = *(const float4*)&gam[tid * 4];
    float4 bv = *(const float4*)&bet[tid * 4];
    float4 ov;
    ov.x = (v.x - mean) * rs * gv.x + bv.x;
    ov.y = (v.y - mean) * rs * gv.y + bv.y;
    ov.z = (v.z - mean) * rs * gv.z + bv.z;
    ov.w = (v.w - mean) * rs * gv.w + bv.w;
    *(float4*)&out[(size_t)row * D_ + tid * 4] = ov;
}

// ---------------- RoPE ----------------
__global__ void rope_kernel(float* __restrict__ buf, int nheads)
{
    int t = blockIdx.x;
    int h = blockIdx.y;
    int j = threadIdx.x;
    int s = t & (S_ - 1);
    float inv = 1.0f / powf(10000.0f, (float)(2 * j) / 64.0f);
    float ang = (float)s * inv;
    float sn, c;
    sincosf(ang, &sn, &c);
    float* p = buf + (size_t)t * (nheads * HD_) + h * HD_;
    float x1 = p[j], x2 = p[j + 32];
    p[j]      = x1 * c - x2 * sn;
    p[j + 32] = x1 * sn + x2 * c;
}

// ---------------- tf32 mma.sync GEMM: C = A[MxK] @ B[KxN] (+epilogue) ---
// Block 128x128, K-chunk 32. 8 warps = 4(M) x 2(N), warp tile 32x64.
// Single smem buffer + register prefetch of next chunk.
#define TBM 128
#define TBN 128
#define TBK 32
#define ASTR 36    // floats; bank = (4g+tg)%32 unique for fragment loads
#define BSTR 136   // floats; bank = (8tg+g)%32 unique

enum { EPI_NONE = 0, EPI_RES = 1, EPI_BIAS_GELU = 2, EPI_BIAS_RES = 3 };

template <int EPI>
__global__ __launch_bounds__(256) void gemm_mma(
    const float* __restrict__ A, const float* __restrict__ Bm,
    const float* __restrict__ bias, const float* __restrict__ res,
    float* __restrict__ C, int M, int N, int K)
{
    __shared__ float As[TBM * ASTR];   // 18432 B
    __shared__ float Bs[TBK * BSTR];   // 17408 B

    int tid = threadIdx.x;
    int wid = tid >> 5, lane = tid & 31;
    int g = lane >> 2, tg = lane & 3;
    int wm = (wid & 3) * 32, wn = (wid >> 2) * 64;
    int m0 = blockIdx.y * TBM, n0 = blockIdx.x * TBN;

    float c[2][8][4];
    #pragma unroll
    for (int mi = 0; mi < 2; mi++)
        #pragma unroll
        for (int ni = 0; ni < 8; ni++)
            #pragma unroll
            for (int e = 0; e < 4; e++) c[mi][ni][e] = 0.f;

    float4 pa[4], pb[4];

    // prefetch chunk kc into registers
    auto ldg = [&](int kc) {
        int k0 = kc * TBK;
        #pragma unroll
        for (int t = 0; t < 4; t++) {
            int i = tid + 256 * t;
            int mm = i >> 3, kq = i & 7;
            pa[t] = *(const float4*)&A[(size_t)(m0 + mm) * K + k0 + kq * 4];
            int kk = i >> 5, nq = i & 31;
            pb[t] = *(const float4*)&Bm[(size_t)(k0 + kk) * N + n0 + nq * 4];
        }
    };
    // store register prefetch into smem (tf32-rounded)
    auto sts = [&]() {
        #pragma unroll
        for (int t = 0; t < 4; t++) {
            int i = tid + 256 * t;
            int mm = i >> 3, kq = i & 7;
            float4 v = pa[t];
            v.x = to_tf32(v.x); v.y = to_tf32(v.y); v.z = to_tf32(v.z); v.w = to_tf32(v.w);
            *(float4*)&As[mm * ASTR + kq * 4] = v;
            int kk = i >> 5, nq = i & 31;
            float4 w = pb[t];
            w.x = to_tf32(w.x); w.y = to_tf32(w.y); w.z = to_tf32(w.z); w.w = to_tf32(w.w);
            *(float4*)&Bs[kk * BSTR + nq * 4] = w;
        }
    };
    auto compute = [&]() {
        #pragma unroll
        for (int ks = 0; ks < 4; ks++) {
            int k0 = ks * 8;
            uint32_t a[2][4], b[8][2];
            #pragma unroll
            for (int mi = 0; mi < 2; mi++) {
                int rb = wm + mi * 16;
                a[mi][0] = __float_as_uint(As[(rb + g)     * ASTR + k0 + tg]);
                a[mi][1] = __float_as_uint(As[(rb + g + 8) * ASTR + k0 + tg]);
                a[mi][2] = __float_as_uint(As[(rb + g)     * ASTR + k0 + tg + 4]);
                a[mi][3] = __float_as_uint(As[(rb + g + 8) * ASTR + k0 + tg + 4]);
            }
            #pragma unroll
            for (int ni = 0; ni < 8; ni++) {
                int col = wn + ni * 8 + g;
                b[ni][0] = __float_as_uint(Bs[(k0 + tg)     * BSTR + col]);
                b[ni][1] = __float_as_uint(Bs[(k0 + tg + 4) * BSTR + col]);
            }
            #pragma unroll
            for (int mi = 0; mi < 2; mi++)
                #pragma unroll
                for (int ni = 0; ni < 8; ni++)
                    mma_tf32_16n8k8(c[mi][ni][0], c[mi][ni][1], c[mi][ni][2], c[mi][ni][3],
                                    a[mi][0], a[mi][1], a[mi][2], a[mi][3],
                                    b[ni][0], b[ni][1]);
        }
    };

    ldg(0); sts();
    __syncthreads();
    int nch = K / TBK;
    for (int cc = 0; cc < nch; cc++) {
        if (cc + 1 < nch) ldg(cc + 1);
        compute();
        __syncthreads();
        if (cc + 1 < nch) { sts(); __syncthreads(); }
    }

    // ---- epilogue: each thread owns rows (g, g+8) of 2 m-tiles, col pairs ----
    #pragma unroll
    for (int mi = 0; mi < 2; mi++) {
        #pragma unroll
        for (int ni = 0; ni < 8; ni++) {
            int ccol = n0 + wn + ni * 8 + 2 * tg;
            #pragma unroll
            for (int hr = 0; hr < 2; hr++) {
                int r = m0 + wm + mi * 16 + g + hr * 8;
                float v0 = c[mi][ni][hr * 2 + 0];
                float v1 = c[mi][ni][hr * 2 + 1];
                size_t idx = (size_t)r * N + ccol;
                if (EPI == EPI_RES) { v0 += res[idx]; v1 += res[idx + 1]; }
                if (EPI == EPI_BIAS_GELU) {
                    float u0 = v0 + bias[ccol], u1 = v1 + bias[ccol + 1];
                    v0 = 0.5f * u0 * (1.f + tanhf(0.7978845608028654f * (u0 + 0.044715f * u0 * u0 * u0)));
                    v1 = 0.5f * u1 * (1.f + tanhf(0.7978845608028654f * (u1 + 0.044715f * u1 * u1 * u1)));
                }
                if (EPI == EPI_BIAS_RES) {
                    v0 += bias[ccol]     + res[idx];
                    v1 += bias[ccol + 1] + res[idx + 1];
                }
                float2 ov = make_float2(v0, v1);
                *(float2*)&C[idx] = ov;
            }
        }
    }
}

// ---------------- causal flash attention (fp32 SIMT) --------------------
#define AQ 64
#define AC 32

__global__ __launch_bounds__(256) void attn_kernel(
    const float* __restrict__ Q, const float* __restrict__ Kg,
    const float* __restrict__ Vg, float* __restrict__ O)
{
    __shared__ float Qs[AQ][HD_ + 1];
    __shared__ float Ks[AC][HD_ + 1];
    __shared__ float Vs[AC][HD_ + 1];
    __shared__ float Ss[AQ][AC + 1];
    __shared__ float mrow[AQ], lrow[AQ], crow[AQ];

    int tid = threadIdx.x;
    int tx = tid & 15, ty = tid >> 4;
    int qt = blockIdx.x, hq = blockIdx.y, b = blockIdx.z;
    int q0 = qt * AQ;
    int kvh = hq & (HKV_ - 1);
    size_t qbase = ((size_t)(b * S_ + q0)) * D_ + hq * HD_;

    #pragma unroll
    for (int r = 0; r < 4; r++) {
        int row = (tid >> 4) + r * 16;
        int c4  = (tid & 15) * 4;
        float4 v = *(const float4*)&Q[qbase + (size_t)row * D_ + c4];
        Qs[row][c4] = v.x; Qs[row][c4 + 1] = v.y; Qs[row][c4 + 2] = v.z; Qs[row][c4 + 3] = v.w;
    }
    if (tid < AQ) { mrow[tid] = -3.0e38f; lrow[tid] = 0.f; }
    float oacc[4][4] = {};
    __syncthreads();

    int ntiles = (q0 + AQ) / AC;
    for (int t = 0; t < ntiles; t++) {
        int kv0 = t * AC;
        #pragma unroll
        for (int r = 0; r < 2; r++) {
            int row = (tid >> 4) + r * 16;
            int c4  = (tid & 15) * 4;
            size_t gidx = ((size_t)(b * S_ + kv0 + row)) * KVD_ + kvh * HD_ + c4;
            float4 kvl = *(const float4*)&Kg[gidx];
            Ks[row][c4] = kvl.x; Ks[row][c4 + 1] = kvl.y; Ks[row][c4 + 2] = kvl.z; Ks[row][c4 + 3] = kvl.w;
            float4 vvl = *(const float4*)&Vg[gidx];
            Vs[row][c4] = vvl.x; Vs[row][c4 + 1] = vvl.y; Vs[row][c4 + 2] = vvl.z; Vs[row][c4 + 3] = vvl.w;
        }
        __syncthreads();

        float sacc[4][2] = {};
        #pragma unroll 8
        for (int k = 0; k < HD_; k++) {
            float a0 = Qs[ty * 4 + 0][k];
            float a1 = Qs[ty * 4 + 1][k];
            float a2 = Qs[ty * 4 + 2][k];
            float a3 = Qs[ty * 4 + 3][k];
            float b0 = Ks[tx * 2 + 0][k];
            float b1 = Ks[tx * 2 + 1][k];
            sacc[0][0] += a0 * b0; sacc[0][1] += a0 * b1;
            sacc[1][0] += a1 * b0; sacc[1][1] += a1 * b1;
            sacc[2][0] += a2 * b0; sacc[2][1] += a2 * b1;
            sacc[3][0] += a3 * b0; sacc[3][1] += a3 * b1;
        }
        #pragma unroll
        for (int i = 0; i < 4; i++)
            #pragma unroll
            for (int j = 0; j < 2; j++) {
                int r = ty * 4 + i, cx = tx * 2 + j;
                int qg = q0 + r, kg = kv0 + cx;
                Ss[r][cx] = sacc[i][j] * 0.125f + (kg <= qg ? 0.f : -1e9f);
            }
        __syncthreads();

        if (tid < AQ) {
            int r = tid;
            float mo = mrow[r];
            float tm = mo;
            #pragma unroll 8
            for (int cx = 0; cx < AC; cx++) tm = fmaxf(tm, Ss[r][cx]);
            float corr = expf(mo - tm);
            float ps = 0.f;
            #pragma unroll 8
            for (int cx = 0; cx < AC; cx++) {
                float p = expf(Ss[r][cx] - tm);
                Ss[r][cx] = p;
                ps += p;
            }
            lrow[r] = lrow[r] * corr + ps;
            mrow[r] = tm;
            crow[r] = corr;
        }
        __syncthreads();

        #pragma unroll
        for (int i = 0; i < 4; i++) {
            float cf = crow[ty * 4 + i];
            #pragma unroll
            for (int j = 0; j < 4; j++) oacc[i][j] *= cf;
        }
        #pragma unroll 8
        for (int k = 0; k < AC; k++) {
            float p0 = Ss[ty * 4 + 0][k];
            float p1 = Ss[ty * 4 + 1][k];
            float p2 = Ss[ty * 4 + 2][k];
            float p3 = Ss[ty * 4 + 3][k];
            float v0 = Vs[k][tx * 4 + 0];
            float v1 = Vs[k][tx * 4 + 1];
            float v2 = Vs[k][tx * 4 + 2];
            float v3 = Vs[k][tx * 4 + 3];
            oacc[0][0] += p0 * v0; oacc[0][1] += p0 * v1; oacc[0][2] += p0 * v2; oacc[0][3] += p0 * v3;
            oacc[1][0] += p1 * v0; oacc[1][1] += p1 * v1; oacc[1][2] += p1 * v2; oacc[1][3] += p1 * v3;
            oacc[2][0] += p2 * v0; oacc[2][1] += p2 * v1; oacc[2][2] += p2 * v2; oacc[2][3] += p2 * v3;
            oacc[3][0] += p3 * v0; oacc[3][1] += p3 * v1; oacc[3][2] += p3 * v2; oacc[3][3] += p3 * v3;
        }
        __syncthreads();
    }

    #pragma unroll
    for (int i = 0; i < 4; i++) {
        int r = ty * 4 + i;
        float inv_l = 1.f / lrow[r];
        float4 ov;
        ov.x = oacc[i][0] * inv_l;
        ov.y = oacc[i][1] * inv_l;
        ov.z = oacc[i][2] * inv_l;
        ov.w = oacc[i][3] * inv_l;
        *(float4*)&O[((size_t)(b * S_ + q0 + r)) * D_ + hq * HD_ + tx * 4] = ov;
    }
}

// ---------------- launch ----------------
extern "C" void kernel_launch(void* const* d_in, const int* in_sizes, int n_in,
                              void* d_out, int out_size)
{
    const float* x    = (const float*)d_in[0];
    const float* wq   = (const float*)d_in[2];
    const float* wk   = (const float*)d_in[3];
    const float* wv   = (const float*)d_in[4];
    const float* wo   = (const float*)d_in[5];
    const float* ln1g = (const float*)d_in[6];
    const float* ln1b = (const float*)d_in[7];
    const float* ln2g = (const float*)d_in[8];
    const float* ln2b = (const float*)d_in[9];
    const float* w1   = (const float*)d_in[10];
    const float* b1   = (const float*)d_in[11];
    const float* w2   = (const float*)d_in[12];
    const float* b2   = (const float*)d_in[13];
    float* out = (float*)d_out;

    float *h, *q, *k, *v, *o, *x2, *mid;
    cudaGetSymbolAddress((void**)&h,   g_h);
    cudaGetSymbolAddress((void**)&q,   g_q);
    cudaGetSymbolAddress((void**)&k,   g_k);
    cudaGetSymbolAddress((void**)&v,   g_v);
    cudaGetSymbolAddress((void**)&o,   g_o);
    cudaGetSymbolAddress((void**)&x2,  g_x2);
    cudaGetSymbolAddress((void**)&mid, g_mid);

    // 1. h = LN1(x)
    ln_kernel<<<M_, 256>>>(x, ln1g, ln1b, h);
    // 2-4. q/k/v projections (tf32 mma.sync)
    gemm_mma<EPI_NONE><<<dim3(D_ / TBN,   M_ / TBM), 256>>>(h, wq, nullptr, nullptr, q, M_, D_,   D_);
    gemm_mma<EPI_NONE><<<dim3(KVD_ / TBN, M_ / TBM), 256>>>(h, wk, nullptr, nullptr, k, M_, KVD_, D_);
    gemm_mma<EPI_NONE><<<dim3(KVD_ / TBN, M_ / TBM), 256>>>(h, wv, nullptr, nullptr, v, M_, KVD_, D_);
    // 5-6. RoPE
    rope_kernel<<<dim3(M_, HQ_),  32>>>(q, HQ_);
    rope_kernel<<<dim3(M_, HKV_), 32>>>(k, HKV_);
    // 7. attention
    attn_kernel<<<dim3(S_ / AQ, HQ_, B_), 256>>>(q, k, v, o);
    // 8. x2 = x + o @ wo
    gemm_mma<EPI_RES><<<dim3(D_ / TBN, M_ / TBM), 256>>>(o, wo, nullptr, x, x2, M_, D_, D_);
    // 9. h2 = LN2(x2)
    ln_kernel<<<M_, 256>>>(x2, ln2g, ln2b, h);
    // 10. mid = gelu(h2 @ w1 + b1)
    gemm_mma<EPI_BIAS_GELU><<<dim3(P_ / TBN, M_ / TBM), 256>>>(h, w1, b1, nullptr, mid, M_, P_, D_);
    // 11. out = x2 + mid @ w2 + b2
    gemm_mma<EPI_BIAS_RES><<<dim3(D_ / TBN, M_ / TBM), 256>>>(mid, w2, b2, x2, out, M_, D_, P_);
}

// round 5
// speedup vs baseline: 2.6031x; 1.5393x over previous
#include <cuda_runtime.h>
#include <math.h>
#include <stdint.h>

// ---------------- problem constants ----------------
#define B_   2
#define S_   2048
#define D_   1024
#define HQ_  16
#define HKV_ 4
#define HD_  64
#define P_   4096
#define M_   (B_ * S_)        // 4096
#define KVD_ (HKV_ * HD_)     // 256

// ---------------- scratch ----------------
__device__ float g_h [M_ * D_];
__device__ float g_q [M_ * D_];
__device__ float g_k [M_ * KVD_];
__device__ float g_v [M_ * KVD_];
__device__ float g_o [M_ * D_];
__device__ float g_x2[M_ * D_];
__device__ float g_mid[M_ * P_];

__device__ __forceinline__ float to_tf32(float x) {
    float r; asm("cvt.rna.tf32.f32 %0, %1;" : "=f"(r) : "f"(x)); return r;
}

__device__ __forceinline__ void mma_tf32_16n8k8(
    float& d0, float& d1, float& d2, float& d3,
    uint32_t a0, uint32_t a1, uint32_t a2, uint32_t a3,
    uint32_t b0, uint32_t b1)
{
    asm volatile(
        "mma.sync.aligned.m16n8k8.row.col.f32.tf32.tf32.f32 "
        "{%0,%1,%2,%3}, {%4,%5,%6,%7}, {%8,%9}, {%0,%1,%2,%3};"
        : "+f"(d0), "+f"(d1), "+f"(d2), "+f"(d3)
        : "r"(a0), "r"(a1), "r"(a2), "r"(a3), "r"(b0), "r"(b1));
}

// ---------------- LayerNorm ----------------
__global__ __launch_bounds__(256) void ln_kernel(
    const float* __restrict__ x, const float* __restrict__ gam,
    const float* __restrict__ bet, float* __restrict__ out)
{
    __shared__ float red[20];
    int row = blockIdx.x;
    int tid = threadIdx.x;
    const float* xr = x + (size_t)row * D_;
    float4 v = *(const float4*)&xr[tid * 4];
    float s  = v.x + v.y + v.z + v.w;
    float sq = v.x * v.x + v.y * v.y + v.z * v.z + v.w * v.w;
    #pragma unroll
    for (int o = 16; o; o >>= 1) {
        s  += __shfl_xor_sync(0xffffffffu, s,  o);
        sq += __shfl_xor_sync(0xffffffffu, sq, o);
    }
    if ((tid & 31) == 0) { red[tid >> 5] = s; red[8 + (tid >> 5)] = sq; }
    __syncthreads();
    if (tid < 32) {
        float a = (tid < 8) ? red[tid]     : 0.f;
        float b = (tid < 8) ? red[8 + tid] : 0.f;
        #pragma unroll
        for (int o = 4; o; o >>= 1) {
            a += __shfl_xor_sync(0xffffffffu, a, o);
            b += __shfl_xor_sync(0xffffffffu, b, o);
        }
        if (tid == 0) { red[16] = a; red[17] = b; }
    }
    __syncthreads();
    float mean = red[16] * (1.f / D_);
    float var  = red[17] * (1.f / D_) - mean * mean;
    float rs   = rsqrtf(var + 1e-5f);
    float4 gv = *(const float4*)&gam[tid * 4];
    float4 bv = *(const float4*)&bet[tid * 4];
    float4 ov;
    ov.x = (v.x - mean) * rs * gv.x + bv.x;
    ov.y = (v.y - mean) * rs * gv.y + bv.y;
    ov.z = (v.z - mean) * rs * gv.z + bv.z;
    ov.w = (v.w - mean) * rs * gv.w + bv.w;
    *(float4*)&out[(size_t)row * D_ + tid * 4] = ov;
}

// ---------------- RoPE ----------------
__global__ void rope_kernel(float* __restrict__ buf, int nheads)
{
    int t = blockIdx.x;
    int h = blockIdx.y;
    int j = threadIdx.x;
    int s = t & (S_ - 1);
    float inv = 1.0f / powf(10000.0f, (float)(2 * j) / 64.0f);
    float ang = (float)s * inv;
    float sn, c;
    sincosf(ang, &sn, &c);
    float* p = buf + (size_t)t * (nheads * HD_) + h * HD_;
    float x1 = p[j], x2 = p[j + 32];
    p[j]      = x1 * c - x2 * sn;
    p[j + 32] = x1 * sn + x2 * c;
}

// ---------------- tf32 mma.sync GEMM (as R4) ----------------------------
#define TBM 128
#define TBN 128
#define TBK 32
#define ASTR 36
#define BSTR 136

enum { EPI_NONE = 0, EPI_RES = 1, EPI_BIAS_GELU = 2, EPI_BIAS_RES = 3 };

template <int EPI>
__global__ __launch_bounds__(256) void gemm_mma(
    const float* __restrict__ A, const float* __restrict__ Bm,
    const float* __restrict__ bias, const float* __restrict__ res,
    float* __restrict__ C, int M, int N, int K)
{
    __shared__ float As[TBM * ASTR];
    __shared__ float Bs[TBK * BSTR];

    int tid = threadIdx.x;
    int wid = tid >> 5, lane = tid & 31;
    int g = lane >> 2, tg = lane & 3;
    int wm = (wid & 3) * 32, wn = (wid >> 2) * 64;
    int m0 = blockIdx.y * TBM, n0 = blockIdx.x * TBN;

    float c[2][8][4];
    #pragma unroll
    for (int mi = 0; mi < 2; mi++)
        #pragma unroll
        for (int ni = 0; ni < 8; ni++)
            #pragma unroll
            for (int e = 0; e < 4; e++) c[mi][ni][e] = 0.f;

    float4 pa[4], pb[4];

    auto ldg = [&](int kc) {
        int k0 = kc * TBK;
        #pragma unroll
        for (int t = 0; t < 4; t++) {
            int i = tid + 256 * t;
            int mm = i >> 3, kq = i & 7;
            pa[t] = *(const float4*)&A[(size_t)(m0 + mm) * K + k0 + kq * 4];
            int kk = i >> 5, nq = i & 31;
            pb[t] = *(const float4*)&Bm[(size_t)(k0 + kk) * N + n0 + nq * 4];
        }
    };
    auto sts = [&]() {
        #pragma unroll
        for (int t = 0; t < 4; t++) {
            int i = tid + 256 * t;
            int mm = i >> 3, kq = i & 7;
            float4 v = pa[t];
            v.x = to_tf32(v.x); v.y = to_tf32(v.y); v.z = to_tf32(v.z); v.w = to_tf32(v.w);
            *(float4*)&As[mm * ASTR + kq * 4] = v;
            int kk = i >> 5, nq = i & 31;
            float4 w = pb[t];
            w.x = to_tf32(w.x); w.y = to_tf32(w.y); w.z = to_tf32(w.z); w.w = to_tf32(w.w);
            *(float4*)&Bs[kk * BSTR + nq * 4] = w;
        }
    };
    auto compute = [&]() {
        #pragma unroll
        for (int ks = 0; ks < 4; ks++) {
            int k0 = ks * 8;
            uint32_t a[2][4], b[8][2];
            #pragma unroll
            for (int mi = 0; mi < 2; mi++) {
                int rb = wm + mi * 16;
                a[mi][0] = __float_as_uint(As[(rb + g)     * ASTR + k0 + tg]);
                a[mi][1] = __float_as_uint(As[(rb + g + 8) * ASTR + k0 + tg]);
                a[mi][2] = __float_as_uint(As[(rb + g)     * ASTR + k0 + tg + 4]);
                a[mi][3] = __float_as_uint(As[(rb + g + 8) * ASTR + k0 + tg + 4]);
            }
            #pragma unroll
            for (int ni = 0; ni < 8; ni++) {
                int col = wn + ni * 8 + g;
                b[ni][0] = __float_as_uint(Bs[(k0 + tg)     * BSTR + col]);
                b[ni][1] = __float_as_uint(Bs[(k0 + tg + 4) * BSTR + col]);
            }
            #pragma unroll
            for (int mi = 0; mi < 2; mi++)
                #pragma unroll
                for (int ni = 0; ni < 8; ni++)
                    mma_tf32_16n8k8(c[mi][ni][0], c[mi][ni][1], c[mi][ni][2], c[mi][ni][3],
                                    a[mi][0], a[mi][1], a[mi][2], a[mi][3],
                                    b[ni][0], b[ni][1]);
        }
    };

    ldg(0); sts();
    __syncthreads();
    int nch = K / TBK;
    for (int cc = 0; cc < nch; cc++) {
        if (cc + 1 < nch) ldg(cc + 1);
        compute();
        __syncthreads();
        if (cc + 1 < nch) { sts(); __syncthreads(); }
    }

    #pragma unroll
    for (int mi = 0; mi < 2; mi++) {
        #pragma unroll
        for (int ni = 0; ni < 8; ni++) {
            int ccol = n0 + wn + ni * 8 + 2 * tg;
            #pragma unroll
            for (int hr = 0; hr < 2; hr++) {
                int r = m0 + wm + mi * 16 + g + hr * 8;
                float v0 = c[mi][ni][hr * 2 + 0];
                float v1 = c[mi][ni][hr * 2 + 1];
                size_t idx = (size_t)r * N + ccol;
                if (EPI == EPI_RES) { v0 += res[idx]; v1 += res[idx + 1]; }
                if (EPI == EPI_BIAS_GELU) {
                    float u0 = v0 + bias[ccol], u1 = v1 + bias[ccol + 1];
                    v0 = 0.5f * u0 * (1.f + tanhf(0.7978845608028654f * (u0 + 0.044715f * u0 * u0 * u0)));
                    v1 = 0.5f * u1 * (1.f + tanhf(0.7978845608028654f * (u1 + 0.044715f * u1 * u1 * u1)));
                }
                if (EPI == EPI_BIAS_RES) {
                    v0 += bias[ccol]     + res[idx];
                    v1 += bias[ccol + 1] + res[idx + 1];
                }
                float2 ov = make_float2(v0, v1);
                *(float2*)&C[idx] = ov;
            }
        }
    }
}

// ---------------- tensor-core causal flash attention --------------------
// Block: 128 q rows x 1 head. 8 warps, warp tile = 16 q x 64 kv.
// kv tiles of 64. Q fragments in registers; K/V/P staged in smem.
#define AQB 128
#define ACB 64
#define KVS 68     // smem row stride (floats)
#define ATTN_SMEM ((2 * ACB * KVS + 8 * 16 * KVS) * 4)   // 69632 B

__global__ __launch_bounds__(256) void attn_tc(
    const float* __restrict__ Q, const float* __restrict__ Kg,
    const float* __restrict__ Vg, float* __restrict__ O)
{
    extern __shared__ float sm[];
    float* Ks = sm;                       // [64][KVS]
    float* Vs = sm + ACB * KVS;           // [64][KVS]
    float* Ps = sm + 2 * ACB * KVS;       // [8][16][KVS]

    int tid = threadIdx.x, w = tid >> 5, lane = tid & 31;
    int g = lane >> 2, tg = lane & 3;
    int qt = blockIdx.x, hq = blockIdx.y, b = blockIdx.z;
    int q0 = qt * AQB;
    int kvh = hq & (HKV_ - 1);
    int wrow = q0 + w * 16;
    float* Pw = Ps + w * 16 * KVS;

    // Q fragments (held in registers for whole kernel)
    uint32_t qf[8][4];
    {
        const float* Qb = Q + ((size_t)(b * S_ + wrow)) * D_ + hq * HD_;
        #pragma unroll
        for (int ks = 0; ks < 8; ks++) {
            qf[ks][0] = __float_as_uint(to_tf32(Qb[(size_t)g       * D_ + ks * 8 + tg]));
            qf[ks][1] = __float_as_uint(to_tf32(Qb[(size_t)(g + 8) * D_ + ks * 8 + tg]));
            qf[ks][2] = __float_as_uint(to_tf32(Qb[(size_t)g       * D_ + ks * 8 + tg + 4]));
            qf[ks][3] = __float_as_uint(to_tf32(Qb[(size_t)(g + 8) * D_ + ks * 8 + tg + 4]));
        }
    }

    float oc[8][4];
    #pragma unroll
    for (int ni = 0; ni < 8; ni++)
        #pragma unroll
        for (int e = 0; e < 4; e++) oc[ni][e] = 0.f;
    float m0r = -1e30f, m1r = -1e30f, l0 = 0.f, l1 = 0.f;

    int ntiles = 2 * qt + 2;
    for (int t = 0; t < ntiles; t++) {
        int kv0 = t * ACB;
        // ---- load K,V tiles (tf32-rounded) ----
        #pragma unroll
        for (int i = 0; i < 4; i++) {
            int s = tid + 256 * i;
            int kv = s >> 4, hd4 = (s & 15) * 4;
            size_t gidx = ((size_t)(b * S_ + kv0 + kv)) * KVD_ + kvh * HD_ + hd4;
            float4 kvv = *(const float4*)&Kg[gidx];
            kvv.x = to_tf32(kvv.x); kvv.y = to_tf32(kvv.y); kvv.z = to_tf32(kvv.z); kvv.w = to_tf32(kvv.w);
            *(float4*)&Ks[kv * KVS + hd4] = kvv;
            float4 vv = *(const float4*)&Vg[gidx];
            vv.x = to_tf32(vv.x); vv.y = to_tf32(vv.y); vv.z = to_tf32(vv.z); vv.w = to_tf32(vv.w);
            *(float4*)&Vs[kv * KVS + hd4] = vv;
        }
        __syncthreads();

        bool active = (kv0 <= wrow + 15);
        if (active) {
            // ---- S = Q @ K^T (16 x 64) ----
            float sc[8][4];
            #pragma unroll
            for (int ni = 0; ni < 8; ni++)
                #pragma unroll
                for (int e = 0; e < 4; e++) sc[ni][e] = 0.f;
            #pragma unroll
            for (int ks = 0; ks < 8; ks++) {
                #pragma unroll
                for (int ni = 0; ni < 8; ni++) {
                    uint32_t b0 = __float_as_uint(Ks[(ni * 8 + g) * KVS + ks * 8 + tg]);
                    uint32_t b1 = __float_as_uint(Ks[(ni * 8 + g) * KVS + ks * 8 + tg + 4]);
                    mma_tf32_16n8k8(sc[ni][0], sc[ni][1], sc[ni][2], sc[ni][3],
                                    qf[ks][0], qf[ks][1], qf[ks][2], qf[ks][3], b0, b1);
                }
            }
            // ---- scale + causal mask ----
            bool diag = (kv0 + ACB > wrow);   // tile touches/crosses the diagonal
            int r0 = wrow + g, r1 = wrow + g + 8;
            #pragma unroll
            for (int ni = 0; ni < 8; ni++) {
                int c0 = kv0 + ni * 8 + 2 * tg, c1 = c0 + 1;
                sc[ni][0] *= 0.125f; sc[ni][1] *= 0.125f;
                sc[ni][2] *= 0.125f; sc[ni][3] *= 0.125f;
                if (diag) {
                    if (c0 > r0) sc[ni][0] = -1e9f;
                    if (c1 > r0) sc[ni][1] = -1e9f;
                    if (c0 > r1) sc[ni][2] = -1e9f;
                    if (c1 > r1) sc[ni][3] = -1e9f;
                }
            }
            // ---- online softmax (rows g, g+8) ----
            float tm0 = -1e30f, tm1 = -1e30f;
            #pragma unroll
            for (int ni = 0; ni < 8; ni++) {
                tm0 = fmaxf(tm0, fmaxf(sc[ni][0], sc[ni][1]));
                tm1 = fmaxf(tm1, fmaxf(sc[ni][2], sc[ni][3]));
            }
            #pragma unroll
            for (int o = 1; o <= 2; o <<= 1) {
                tm0 = fmaxf(tm0, __shfl_xor_sync(0xffffffffu, tm0, o));
                tm1 = fmaxf(tm1, __shfl_xor_sync(0xffffffffu, tm1, o));
            }
            float mn0 = fmaxf(m0r, tm0), mn1 = fmaxf(m1r, tm1);
            float corr0 = __expf(m0r - mn0), corr1 = __expf(m1r - mn1);
            float ps0 = 0.f, ps1 = 0.f;
            #pragma unroll
            for (int ni = 0; ni < 8; ni++) {
                float p0 = __expf(sc[ni][0] - mn0);
                float p1 = __expf(sc[ni][1] - mn0);
                float p2 = __expf(sc[ni][2] - mn1);
                float p3 = __expf(sc[ni][3] - mn1);
                ps0 += p0 + p1; ps1 += p2 + p3;
                int cc = ni * 8 + 2 * tg;
                *(float2*)&Pw[g * KVS + cc]       = make_float2(to_tf32(p0), to_tf32(p1));
                *(float2*)&Pw[(g + 8) * KVS + cc] = make_float2(to_tf32(p2), to_tf32(p3));
            }
            #pragma unroll
            for (int o = 1; o <= 2; o <<= 1) {
                ps0 += __shfl_xor_sync(0xffffffffu, ps0, o);
                ps1 += __shfl_xor_sync(0xffffffffu, ps1, o);
            }
            l0 = l0 * corr0 + ps0; l1 = l1 * corr1 + ps1;
            m0r = mn0; m1r = mn1;
            #pragma unroll
            for (int ni = 0; ni < 8; ni++) {
                oc[ni][0] *= corr0; oc[ni][1] *= corr0;
                oc[ni][2] *= corr1; oc[ni][3] *= corr1;
            }
            __syncwarp();
            // ---- O += P @ V ----
            #pragma unroll
            for (int ks = 0; ks < 8; ks++) {
                uint32_t a0 = __float_as_uint(Pw[g       * KVS + ks * 8 + tg]);
                uint32_t a1 = __float_as_uint(Pw[(g + 8) * KVS + ks * 8 + tg]);
                uint32_t a2 = __float_as_uint(Pw[g       * KVS + ks * 8 + tg + 4]);
                uint32_t a3 = __float_as_uint(Pw[(g + 8) * KVS + ks * 8 + tg + 4]);
                #pragma unroll
                for (int ni = 0; ni < 8; ni++) {
                    uint32_t b0 = __float_as_uint(Vs[(ks * 8 + tg)     * KVS + ni * 8 + g]);
                    uint32_t b1 = __float_as_uint(Vs[(ks * 8 + tg + 4) * KVS + ni * 8 + g]);
                    mma_tf32_16n8k8(oc[ni][0], oc[ni][1], oc[ni][2], oc[ni][3],
                                    a0, a1, a2, a3, b0, b1);
                }
            }
        }
        __syncthreads();
    }

    // ---- epilogue ----
    float il0 = 1.f / l0, il1 = 1.f / l1;
    size_t ob0 = ((size_t)(b * S_ + wrow + g))     * D_ + hq * HD_;
    size_t ob1 = ((size_t)(b * S_ + wrow + g + 8)) * D_ + hq * HD_;
    #pragma unroll
    for (int ni = 0; ni < 8; ni++) {
        int cc = ni * 8 + 2 * tg;
        *(float2*)&O[ob0 + cc] = make_float2(oc[ni][0] * il0, oc[ni][1] * il0);
        *(float2*)&O[ob1 + cc] = make_float2(oc[ni][2] * il1, oc[ni][3] * il1);
    }
}

// ---------------- launch ----------------
extern "C" void kernel_launch(void* const* d_in, const int* in_sizes, int n_in,
                              void* d_out, int out_size)
{
    const float* x    = (const float*)d_in[0];
    const float* wq   = (const float*)d_in[2];
    const float* wk   = (const float*)d_in[3];
    const float* wv   = (const float*)d_in[4];
    const float* wo   = (const float*)d_in[5];
    const float* ln1g = (const float*)d_in[6];
    const float* ln1b = (const float*)d_in[7];
    const float* ln2g = (const float*)d_in[8];
    const float* ln2b = (const float*)d_in[9];
    const float* w1   = (const float*)d_in[10];
    const float* b1   = (const float*)d_in[11];
    const float* w2   = (const float*)d_in[12];
    const float* b2   = (const float*)d_in[13];
    float* out = (float*)d_out;

    float *h, *q, *k, *v, *o, *x2, *mid;
    cudaGetSymbolAddress((void**)&h,   g_h);
    cudaGetSymbolAddress((void**)&q,   g_q);
    cudaGetSymbolAddress((void**)&k,   g_k);
    cudaGetSymbolAddress((void**)&v,   g_v);
    cudaGetSymbolAddress((void**)&o,   g_o);
    cudaGetSymbolAddress((void**)&x2,  g_x2);
    cudaGetSymbolAddress((void**)&mid, g_mid);

    cudaFuncSetAttribute(attn_tc, cudaFuncAttributeMaxDynamicSharedMemorySize, ATTN_SMEM);

    // 1. h = LN1(x)
    ln_kernel<<<M_, 256>>>(x, ln1g, ln1b, h);
    // 2-4. q/k/v projections (tf32 mma.sync)
    gemm_mma<EPI_NONE><<<dim3(D_ / TBN,   M_ / TBM), 256>>>(h, wq, nullptr, nullptr, q, M_, D_,   D_);
    gemm_mma<EPI_NONE><<<dim3(KVD_ / TBN, M_ / TBM), 256>>>(h, wk, nullptr, nullptr, k, M_, KVD_, D_);
    gemm_mma<EPI_NONE><<<dim3(KVD_ / TBN, M_ / TBM), 256>>>(h, wv, nullptr, nullptr, v, M_, KVD_, D_);
    // 5-6. RoPE
    rope_kernel<<<dim3(M_, HQ_),  32>>>(q, HQ_);
    rope_kernel<<<dim3(M_, HKV_), 32>>>(k, HKV_);
    // 7. attention (tensor cores)
    attn_tc<<<dim3(S_ / AQB, HQ_, B_), 256, ATTN_SMEM>>>(q, k, v, o);
    // 8. x2 = x + o @ wo
    gemm_mma<EPI_RES><<<dim3(D_ / TBN, M_ / TBM), 256>>>(o, wo, nullptr, x, x2, M_, D_, D_);
    // 9. h2 = LN2(x2)
    ln_kernel<<<M_, 256>>>(x2, ln2g, ln2b, h);
    // 10. mid = gelu(h2 @ w1 + b1)
    gemm_mma<EPI_BIAS_GELU><<<dim3(P_ / TBN, M_ / TBM), 256>>>(h, w1, b1, nullptr, mid, M_, P_, D_);
    // 11. out = x2 + mid @ w2 + b2
    gemm_mma<EPI_BIAS_RES><<<dim3(D_ / TBN, M_ / TBM), 256>>>(mid, w2, b2, x2, out, M_, D_, P_);
}

// round 6
// speedup vs baseline: 3.3851x; 1.3004x over previous
#include <cuda_runtime.h>
#include <math.h>
#include <stdint.h>

// ---------------- problem constants ----------------
#define B_   2
#define S_   2048
#define D_   1024
#define HQ_  16
#define HKV_ 4
#define HD_  64
#define P_   4096
#define M_   (B_ * S_)        // 4096
#define KVD_ (HKV_ * HD_)     // 256

// ---------------- scratch ----------------
__device__ float g_h [M_ * D_];
__device__ float g_q [M_ * D_];
__device__ float g_k [M_ * KVD_];
__device__ float g_v [M_ * KVD_];
__device__ float g_o [M_ * D_];
__device__ float g_x2[M_ * D_];
__device__ float g_mid[M_ * P_];
// tf32-rounded weights
__device__ float g_wq[D_ * D_];
__device__ float g_wk[D_ * KVD_];
__device__ float g_wv[D_ * KVD_];
__device__ float g_wo[D_ * D_];
__device__ float g_w1[D_ * P_];
__device__ float g_w2[P_ * D_];

__device__ __forceinline__ float to_tf32(float x) {
    float r; asm("cvt.rna.tf32.f32 %0, %1;" : "=f"(r) : "f"(x)); return r;
}

__device__ __forceinline__ void mma_tf32_16n8k8(
    float& d0, float& d1, float& d2, float& d3,
    uint32_t a0, uint32_t a1, uint32_t a2, uint32_t a3,
    uint32_t b0, uint32_t b1)
{
    asm volatile(
        "mma.sync.aligned.m16n8k8.row.col.f32.tf32.tf32.f32 "
        "{%0,%1,%2,%3}, {%4,%5,%6,%7}, {%8,%9}, {%0,%1,%2,%3};"
        : "+f"(d0), "+f"(d1), "+f"(d2), "+f"(d3)
        : "r"(a0), "r"(a1), "r"(a2), "r"(a3), "r"(b0), "r"(b1));
}

__device__ __forceinline__ void cp_async16(uint32_t s, const void* g) {
    asm volatile("cp.async.cg.shared.global [%0], [%1], 16;" :: "r"(s), "l"(g));
}
__device__ __forceinline__ void cp_commit() { asm volatile("cp.async.commit_group;" ::: "memory"); }
__device__ __forceinline__ void cp_wait0()  { asm volatile("cp.async.wait_group 0;" ::: "memory"); }
__device__ __forceinline__ void cp_wait1()  { asm volatile("cp.async.wait_group 1;" ::: "memory"); }

// ---------------- weight rounding pre-pass ----------------
__global__ void round_w(const float* __restrict__ s, float* __restrict__ d, int n4)
{
    int i = blockIdx.x * blockDim.x + threadIdx.x;
    if (i < n4) {
        float4 v = *(const float4*)&s[i * 4];
        v.x = to_tf32(v.x); v.y = to_tf32(v.y); v.z = to_tf32(v.z); v.w = to_tf32(v.w);
        *(float4*)&d[i * 4] = v;
    }
}

// ---------------- LayerNorm (tf32-rounded output) ----------------
__global__ __launch_bounds__(256) void ln_kernel(
    const float* __restrict__ x, const float* __restrict__ gam,
    const float* __restrict__ bet, float* __restrict__ out)
{
    __shared__ float red[20];
    int row = blockIdx.x;
    int tid = threadIdx.x;
    const float* xr = x + (size_t)row * D_;
    float4 v = *(const float4*)&xr[tid * 4];
    float s  = v.x + v.y + v.z + v.w;
    float sq = v.x * v.x + v.y * v.y + v.z * v.z + v.w * v.w;
    #pragma unroll
    for (int o = 16; o; o >>= 1) {
        s  += __shfl_xor_sync(0xffffffffu, s,  o);
        sq += __shfl_xor_sync(0xffffffffu, sq, o);
    }
    if ((tid & 31) == 0) { red[tid >> 5] = s; red[8 + (tid >> 5)] = sq; }
    __syncthreads();
    if (tid < 32) {
        float a = (tid < 8) ? red[tid]     : 0.f;
        float b = (tid < 8) ? red[8 + tid] : 0.f;
        #pragma unroll
        for (int o = 4; o; o >>= 1) {
            a += __shfl_xor_sync(0xffffffffu, a, o);
            b += __shfl_xor_sync(0xffffffffu, b, o);
        }
        if (tid == 0) { red[16] = a; red[17] = b; }
    }
    __syncthreads();
    float mean = red[16] * (1.f / D_);
    float var  = red[17] * (1.f / D_) - mean * mean;
    float rs   = rsqrtf(var + 1e-5f);
    float4 gv = *(const float4*)&gam[tid * 4];
    float4 bv = *(const float4*)&bet[tid * 4];
    float4 ov;
    ov.x = to_tf32((v.x - mean) * rs * gv.x + bv.x);
    ov.y = to_tf32((v.y - mean) * rs * gv.y + bv.y);
    ov.z = to_tf32((v.z - mean) * rs * gv.z + bv.z);
    ov.w = to_tf32((v.w - mean) * rs * gv.w + bv.w);
    *(float4*)&out[(size_t)row * D_ + tid * 4] = ov;
}

// ---------------- RoPE ----------------
__global__ void rope_kernel(float* __restrict__ buf, int nheads)
{
    int t = blockIdx.x;
    int h = blockIdx.y;
    int j = threadIdx.x;
    int s = t & (S_ - 1);
    float inv = 1.0f / powf(10000.0f, (float)(2 * j) / 64.0f);
    float ang = (float)s * inv;
    float sn, c;
    sincosf(ang, &sn, &c);
    float* p = buf + (size_t)t * (nheads * HD_) + h * HD_;
    float x1 = p[j], x2 = p[j + 32];
    p[j]      = x1 * c - x2 * sn;
    p[j + 32] = x1 * sn + x2 * c;
}

// ---------------- cp.async 3-stage tf32 GEMM -----------------------------
#define TBM 128
#define TBN 128
#define TBK 32
#define ASTR 36
#define BSTR 136
#define ASZ (TBM * ASTR)       // floats per A stage
#define BSZ (TBK * BSTR)       // floats per B stage
#define STG (ASZ + BSZ)
#define GEMM_SMEM (3 * STG * 4)    // 107520 B

enum { EPI_NONE = 0, EPI_RES = 1, EPI_BIAS_GELU = 2, EPI_BIAS_RES = 3 };

template <int EPI>
__device__ __forceinline__ void gemm_body(
    const float* __restrict__ A, const float* __restrict__ Bm,
    const float* __restrict__ bias, const float* __restrict__ res,
    float* __restrict__ C, int M, int N, int K, int m0, int n0, float* sm)
{
    int tid = threadIdx.x;
    int wid = tid >> 5, lane = tid & 31;
    int g = lane >> 2, tg = lane & 3;
    int wm = (wid & 3) * 32, wn = (wid >> 2) * 64;
    uint32_t smb = (uint32_t)__cvta_generic_to_shared(sm);

    auto issue = [&](int kc, int st) {
        int k0 = kc * TBK;
        uint32_t ab = smb + (uint32_t)(st * STG) * 4u;
        uint32_t bb = ab + ASZ * 4u;
        #pragma unroll
        for (int t = 0; t < 4; t++) {
            int i = tid + 256 * t;
            int mm = i >> 3, kq = i & 7;
            cp_async16(ab + (uint32_t)(mm * ASTR + kq * 4) * 4u,
                       &A[(size_t)(m0 + mm) * K + k0 + kq * 4]);
            int kk = i >> 5, nq = i & 31;
            cp_async16(bb + (uint32_t)(kk * BSTR + nq * 4) * 4u,
                       &Bm[(size_t)(k0 + kk) * N + n0 + nq * 4]);
        }
        cp_commit();
    };

    float c[2][8][4];
    #pragma unroll
    for (int mi = 0; mi < 2; mi++)
        #pragma unroll
        for (int ni = 0; ni < 8; ni++)
            #pragma unroll
            for (int e = 0; e < 4; e++) c[mi][ni][e] = 0.f;

    int nch = K / TBK;
    issue(0, 0);
    issue(1, 1);

    for (int cc = 0; cc < nch; cc++) {
        if (cc + 1 < nch) cp_wait1(); else cp_wait0();
        __syncthreads();
        if (cc + 2 < nch) issue(cc + 2, (cc + 2) % 3);
        float* As = sm + (cc % 3) * STG;
        float* Bs = As + ASZ;
        #pragma unroll
        for (int ks = 0; ks < 4; ks++) {
            int k0 = ks * 8;
            uint32_t a[2][4], b[8][2];
            #pragma unroll
            for (int mi = 0; mi < 2; mi++) {
                int rb = wm + mi * 16;
                a[mi][0] = __float_as_uint(As[(rb + g)     * ASTR + k0 + tg]);
                a[mi][1] = __float_as_uint(As[(rb + g + 8) * ASTR + k0 + tg]);
                a[mi][2] = __float_as_uint(As[(rb + g)     * ASTR + k0 + tg + 4]);
                a[mi][3] = __float_as_uint(As[(rb + g + 8) * ASTR + k0 + tg + 4]);
            }
            #pragma unroll
            for (int ni = 0; ni < 8; ni++) {
                int col = wn + ni * 8 + g;
                b[ni][0] = __float_as_uint(Bs[(k0 + tg)     * BSTR + col]);
                b[ni][1] = __float_as_uint(Bs[(k0 + tg + 4) * BSTR + col]);
            }
            #pragma unroll
            for (int mi = 0; mi < 2; mi++)
                #pragma unroll
                for (int ni = 0; ni < 8; ni++)
                    mma_tf32_16n8k8(c[mi][ni][0], c[mi][ni][1], c[mi][ni][2], c[mi][ni][3],
                                    a[mi][0], a[mi][1], a[mi][2], a[mi][3],
                                    b[ni][0], b[ni][1]);
        }
        __syncthreads();
    }

    #pragma unroll
    for (int mi = 0; mi < 2; mi++) {
        #pragma unroll
        for (int ni = 0; ni < 8; ni++) {
            int ccol = n0 + wn + ni * 8 + 2 * tg;
            #pragma unroll
            for (int hr = 0; hr < 2; hr++) {
                int r = m0 + wm + mi * 16 + g + hr * 8;
                float v0 = c[mi][ni][hr * 2 + 0];
                float v1 = c[mi][ni][hr * 2 + 1];
                size_t idx = (size_t)r * N + ccol;
                if (EPI == EPI_RES) { v0 += res[idx]; v1 += res[idx + 1]; }
                if (EPI == EPI_BIAS_GELU) {
                    float u0 = v0 + bias[ccol], u1 = v1 + bias[ccol + 1];
                    float z0 = 1.5957691216057308f * (u0 + 0.044715f * u0 * u0 * u0);
                    float z1 = 1.5957691216057308f * (u1 + 0.044715f * u1 * u1 * u1);
                    v0 = to_tf32(__fdividef(u0, 1.f + __expf(-z0)));
                    v1 = to_tf32(__fdividef(u1, 1.f + __expf(-z1)));
                }
                if (EPI == EPI_BIAS_RES) {
                    v0 += bias[ccol]     + res[idx];
                    v1 += bias[ccol + 1] + res[idx + 1];
                }
                *(float2*)&C[idx] = make_float2(v0, v1);
            }
        }
    }
}

template <int EPI>
__global__ __launch_bounds__(256) void gemm_mma(
    const float* __restrict__ A, const float* __restrict__ Bm,
    const float* __restrict__ bias, const float* __restrict__ res,
    float* __restrict__ C, int M, int N, int K)
{
    extern __shared__ float sm[];
    gemm_body<EPI>(A, Bm, bias, res, C, M, N, K,
                   blockIdx.y * TBM, blockIdx.x * TBN, sm);
}

// fused QKV: grid (12, 32). bx<8 -> wq, bx 8-9 -> wk, bx 10-11 -> wv.
__global__ __launch_bounds__(256) void qkv_gemm(
    const float* __restrict__ h,
    const float* __restrict__ wq, const float* __restrict__ wk, const float* __restrict__ wv,
    float* __restrict__ q, float* __restrict__ k, float* __restrict__ v)
{
    extern __shared__ float sm[];
    int bx = blockIdx.x;
    const float* Bm; float* C; int N, n0;
    if (bx < 8)       { Bm = wq; C = q; N = D_;   n0 = bx * 128; }
    else if (bx < 10) { Bm = wk; C = k; N = KVD_; n0 = (bx - 8) * 128; }
    else              { Bm = wv; C = v; N = KVD_; n0 = (bx - 10) * 128; }
    gemm_body<EPI_NONE>(h, Bm, nullptr, nullptr, C, M_, N, D_,
                        blockIdx.y * TBM, n0, sm);
}

// ---------------- tensor-core causal flash attention --------------------
#define AQB 128
#define ACB 64
#define KVS 68
#define ATTN_SMEM ((2 * ACB * KVS + 8 * 16 * KVS) * 4)   // 69632 B

__global__ __launch_bounds__(256) void attn_tc(
    const float* __restrict__ Q, const float* __restrict__ Kg,
    const float* __restrict__ Vg, float* __restrict__ O)
{
    extern __shared__ float sm[];
    float* Ks = sm;
    float* Vs = sm + ACB * KVS;
    float* Ps = sm + 2 * ACB * KVS;

    int tid = threadIdx.x, w = tid >> 5, lane = tid & 31;
    int g = lane >> 2, tg = lane & 3;
    int qt = blockIdx.x, hq = blockIdx.y, b = blockIdx.z;
    int q0 = qt * AQB;
    int kvh = hq & (HKV_ - 1);
    int wrow = q0 + w * 16;
    float* Pw = Ps + w * 16 * KVS;

    uint32_t qf[8][4];
    {
        const float* Qb = Q + ((size_t)(b * S_ + wrow)) * D_ + hq * HD_;
        #pragma unroll
        for (int ks = 0; ks < 8; ks++) {
            qf[ks][0] = __float_as_uint(to_tf32(Qb[(size_t)g       * D_ + ks * 8 + tg]));
            qf[ks][1] = __float_as_uint(to_tf32(Qb[(size_t)(g + 8) * D_ + ks * 8 + tg]));
            qf[ks][2] = __float_as_uint(to_tf32(Qb[(size_t)g       * D_ + ks * 8 + tg + 4]));
            qf[ks][3] = __float_as_uint(to_tf32(Qb[(size_t)(g + 8) * D_ + ks * 8 + tg + 4]));
        }
    }

    float oc[8][4];
    #pragma unroll
    for (int ni = 0; ni < 8; ni++)
        #pragma unroll
        for (int e = 0; e < 4; e++) oc[ni][e] = 0.f;
    float m0r = -1e30f, m1r = -1e30f, l0 = 0.f, l1 = 0.f;

    int ntiles = 2 * qt + 2;
    for (int t = 0; t < ntiles; t++) {
        int kv0 = t * ACB;
        #pragma unroll
        for (int i = 0; i < 4; i++) {
            int s = tid + 256 * i;
            int kv = s >> 4, hd4 = (s & 15) * 4;
            size_t gidx = ((size_t)(b * S_ + kv0 + kv)) * KVD_ + kvh * HD_ + hd4;
            float4 kvv = *(const float4*)&Kg[gidx];
            kvv.x = to_tf32(kvv.x); kvv.y = to_tf32(kvv.y); kvv.z = to_tf32(kvv.z); kvv.w = to_tf32(kvv.w);
            *(float4*)&Ks[kv * KVS + hd4] = kvv;
            float4 vv = *(const float4*)&Vg[gidx];
            vv.x = to_tf32(vv.x); vv.y = to_tf32(vv.y); vv.z = to_tf32(vv.z); vv.w = to_tf32(vv.w);
            *(float4*)&Vs[kv * KVS + hd4] = vv;
        }
        __syncthreads();

        bool active = (kv0 <= wrow + 15);
        if (active) {
            float sc[8][4];
            #pragma unroll
            for (int ni = 0; ni < 8; ni++)
                #pragma unroll
                for (int e = 0; e < 4; e++) sc[ni][e] = 0.f;
            #pragma unroll
            for (int ks = 0; ks < 8; ks++) {
                #pragma unroll
                for (int ni = 0; ni < 8; ni++) {
                    uint32_t b0 = __float_as_uint(Ks[(ni * 8 + g) * KVS + ks * 8 + tg]);
                    uint32_t b1 = __float_as_uint(Ks[(ni * 8 + g) * KVS + ks * 8 + tg + 4]);
                    mma_tf32_16n8k8(sc[ni][0], sc[ni][1], sc[ni][2], sc[ni][3],
                                    qf[ks][0], qf[ks][1], qf[ks][2], qf[ks][3], b0, b1);
                }
            }
            bool diag = (kv0 + ACB > wrow);
            int r0 = wrow + g, r1 = wrow + g + 8;
            #pragma unroll
            for (int ni = 0; ni < 8; ni++) {
                int c0 = kv0 + ni * 8 + 2 * tg, c1 = c0 + 1;
                sc[ni][0] *= 0.125f; sc[ni][1] *= 0.125f;
                sc[ni][2] *= 0.125f; sc[ni][3] *= 0.125f;
                if (diag) {
                    if (c0 > r0) sc[ni][0] = -1e9f;
                    if (c1 > r0) sc[ni][1] = -1e9f;
                    if (c0 > r1) sc[ni][2] = -1e9f;
                    if (c1 > r1) sc[ni][3] = -1e9f;
                }
            }
            float tm0 = -1e30f, tm1 = -1e30f;
            #pragma unroll
            for (int ni = 0; ni < 8; ni++) {
                tm0 = fmaxf(tm0, fmaxf(sc[ni][0], sc[ni][1]));
                tm1 = fmaxf(tm1, fmaxf(sc[ni][2], sc[ni][3]));
            }
            #pragma unroll
            for (int o = 1; o <= 2; o <<= 1) {
                tm0 = fmaxf(tm0, __shfl_xor_sync(0xffffffffu, tm0, o));
                tm1 = fmaxf(tm1, __shfl_xor_sync(0xffffffffu, tm1, o));
            }
            float mn0 = fmaxf(m0r, tm0), mn1 = fmaxf(m1r, tm1);
            float corr0 = __expf(m0r - mn0), corr1 = __expf(m1r - mn1);
            float ps0 = 0.f, ps1 = 0.f;
            #pragma unroll
            for (int ni = 0; ni < 8; ni++) {
                float p0 = __expf(sc[ni][0] - mn0);
                float p1 = __expf(sc[ni][1] - mn0);
                float p2 = __expf(sc[ni][2] - mn1);
                float p3 = __expf(sc[ni][3] - mn1);
                ps0 += p0 + p1; ps1 += p2 + p3;
                int cc = ni * 8 + 2 * tg;
                *(float2*)&Pw[g * KVS + cc]       = make_float2(to_tf32(p0), to_tf32(p1));
                *(float2*)&Pw[(g + 8) * KVS + cc] = make_float2(to_tf32(p2), to_tf32(p3));
            }
            #pragma unroll
            for (int o = 1; o <= 2; o <<= 1) {
                ps0 += __shfl_xor_sync(0xffffffffu, ps0, o);
                ps1 += __shfl_xor_sync(0xffffffffu, ps1, o);
            }
            l0 = l0 * corr0 + ps0; l1 = l1 * corr1 + ps1;
            m0r = mn0; m1r = mn1;
            #pragma unroll
            for (int ni = 0; ni < 8; ni++) {
                oc[ni][0] *= corr0; oc[ni][1] *= corr0;
                oc[ni][2] *= corr1; oc[ni][3] *= corr1;
            }
            __syncwarp();
            #pragma unroll
            for (int ks = 0; ks < 8; ks++) {
                uint32_t a0 = __float_as_uint(Pw[g       * KVS + ks * 8 + tg]);
                uint32_t a1 = __float_as_uint(Pw[(g + 8) * KVS + ks * 8 + tg]);
                uint32_t a2 = __float_as_uint(Pw[g       * KVS + ks * 8 + tg + 4]);
                uint32_t a3 = __float_as_uint(Pw[(g + 8) * KVS + ks * 8 + tg + 4]);
                #pragma unroll
                for (int ni = 0; ni < 8; ni++) {
                    uint32_t b0 = __float_as_uint(Vs[(ks * 8 + tg)     * KVS + ni * 8 + g]);
                    uint32_t b1 = __float_as_uint(Vs[(ks * 8 + tg + 4) * KVS + ni * 8 + g]);
                    mma_tf32_16n8k8(oc[ni][0], oc[ni][1], oc[ni][2], oc[ni][3],
                                    a0, a1, a2, a3, b0, b1);
                }
            }
        }
        __syncthreads();
    }

    float il0 = 1.f / l0, il1 = 1.f / l1;
    size_t ob0 = ((size_t)(b * S_ + wrow + g))     * D_ + hq * HD_;
    size_t ob1 = ((size_t)(b * S_ + wrow + g + 8)) * D_ + hq * HD_;
    #pragma unroll
    for (int ni = 0; ni < 8; ni++) {
        int cc = ni * 8 + 2 * tg;
        *(float2*)&O[ob0 + cc] = make_float2(to_tf32(oc[ni][0] * il0), to_tf32(oc[ni][1] * il0));
        *(float2*)&O[ob1 + cc] = make_float2(to_tf32(oc[ni][2] * il1), to_tf32(oc[ni][3] * il1));
    }
}

// ---------------- launch ----------------
extern "C" void kernel_launch(void* const* d_in, const int* in_sizes, int n_in,
                              void* d_out, int out_size)
{
    const float* x    = (const float*)d_in[0];
    const float* wq   = (const float*)d_in[2];
    const float* wk   = (const float*)d_in[3];
    const float* wv   = (const float*)d_in[4];
    const float* wo   = (const float*)d_in[5];
    const float* ln1g = (const float*)d_in[6];
    const float* ln1b = (const float*)d_in[7];
    const float* ln2g = (const float*)d_in[8];
    const float* ln2b = (const float*)d_in[9];
    const float* w1   = (const float*)d_in[10];
    const float* b1   = (const float*)d_in[11];
    const float* w2   = (const float*)d_in[12];
    const float* b2   = (const float*)d_in[13];
    float* out = (float*)d_out;

    float *h, *q, *k, *v, *o, *x2, *mid;
    float *rwq, *rwk, *rwv, *rwo, *rw1, *rw2;
    cudaGetSymbolAddress((void**)&h,   g_h);
    cudaGetSymbolAddress((void**)&q,   g_q);
    cudaGetSymbolAddress((void**)&k,   g_k);
    cudaGetSymbolAddress((void**)&v,   g_v);
    cudaGetSymbolAddress((void**)&o,   g_o);
    cudaGetSymbolAddress((void**)&x2,  g_x2);
    cudaGetSymbolAddress((void**)&mid, g_mid);
    cudaGetSymbolAddress((void**)&rwq, g_wq);
    cudaGetSymbolAddress((void**)&rwk, g_wk);
    cudaGetSymbolAddress((void**)&rwv, g_wv);
    cudaGetSymbolAddress((void**)&rwo, g_wo);
    cudaGetSymbolAddress((void**)&rw1, g_w1);
    cudaGetSymbolAddress((void**)&rw2, g_w2);

    cudaFuncSetAttribute(attn_tc,  cudaFuncAttributeMaxDynamicSharedMemorySize, ATTN_SMEM);
    cudaFuncSetAttribute(qkv_gemm, cudaFuncAttributeMaxDynamicSharedMemorySize, GEMM_SMEM);
    cudaFuncSetAttribute(gemm_mma<EPI_RES>,       cudaFuncAttributeMaxDynamicSharedMemorySize, GEMM_SMEM);
    cudaFuncSetAttribute(gemm_mma<EPI_BIAS_GELU>, cudaFuncAttributeMaxDynamicSharedMemorySize, GEMM_SMEM);
    cudaFuncSetAttribute(gemm_mma<EPI_BIAS_RES>,  cudaFuncAttributeMaxDynamicSharedMemorySize, GEMM_SMEM);

    // 0. round weights to tf32 (scratch)
    round_w<<<(D_ * D_ / 4 + 255) / 256, 256>>>(wq, rwq, D_ * D_ / 4);
    round_w<<<(D_ * KVD_ / 4 + 255) / 256, 256>>>(wk, rwk, D_ * KVD_ / 4);
    round_w<<<(D_ * KVD_ / 4 + 255) / 256, 256>>>(wv, rwv, D_ * KVD_ / 4);
    round_w<<<(D_ * D_ / 4 + 255) / 256, 256>>>(wo, rwo, D_ * D_ / 4);
    round_w<<<(D_ * P_ / 4 + 255) / 256, 256>>>(w1, rw1, D_ * P_ / 4);
    round_w<<<(P_ * D_ / 4 + 255) / 256, 256>>>(w2, rw2, P_ * D_ / 4);

    // 1. h = LN1(x)  (tf32-rounded)
    ln_kernel<<<M_, 256>>>(x, ln1g, ln1b, h);
    // 2. fused q/k/v projection
    qkv_gemm<<<dim3(12, M_ / TBM), 256, GEMM_SMEM>>>(h, rwq, rwk, rwv, q, k, v);
    // 3-4. RoPE
    rope_kernel<<<dim3(M_, HQ_),  32>>>(q, HQ_);
    rope_kernel<<<dim3(M_, HKV_), 32>>>(k, HKV_);
    // 5. attention
    attn_tc<<<dim3(S_ / AQB, HQ_, B_), 256, ATTN_SMEM>>>(q, k, v, o);
    // 6. x2 = x + o @ wo
    gemm_mma<EPI_RES><<<dim3(D_ / TBN, M_ / TBM), 256, GEMM_SMEM>>>(o, rwo, nullptr, x, x2, M_, D_, D_);
    // 7. h2 = LN2(x2)
    ln_kernel<<<M_, 256>>>(x2, ln2g, ln2b, h);
    // 8. mid = gelu(h2 @ w1 + b1)  (tf32-rounded)
    gemm_mma<EPI_BIAS_GELU><<<dim3(P_ / TBN, M_ / TBM), 256, GEMM_SMEM>>>(h, rw1, b1, nullptr, mid, M_, P_, D_);
    // 9. out = x2 + mid @ w2 + b2
    gemm_mma<EPI_BIAS_RES><<<dim3(D_ / TBN, M_ / TBM), 256, GEMM_SMEM>>>(mid, rw2, b2, x2, out, M_, D_, P_);
}

// round 8
// speedup vs baseline: 3.6171x; 1.0686x over previous
#include <cuda_runtime.h>
#include <math.h>
#include <stdint.h>

// ---------------- problem constants ----------------
#define B_   2
#define S_   2048
#define D_   1024
#define HQ_  16
#define HKV_ 4
#define HD_  64
#define P_   4096
#define M_   (B_ * S_)        // 4096
#define KVD_ (HKV_ * HD_)     // 256

// ---------------- scratch ----------------
__device__ float g_h [M_ * D_];
__device__ float g_q [M_ * D_];
__device__ float g_k [M_ * KVD_];
__device__ float g_v [M_ * KVD_];
__device__ float g_o [M_ * D_];
__device__ float g_x2[M_ * D_];
__device__ float g_mid[M_ * P_];
// tf32-rounded weights
__device__ float g_wq[D_ * D_];
__device__ float g_wk[D_ * KVD_];
__device__ float g_wv[D_ * KVD_];
__device__ float g_wo[D_ * D_];
__device__ float g_w1[D_ * P_];
__device__ float g_w2[P_ * D_];

__device__ __forceinline__ float to_tf32(float x) {
    float r; asm("cvt.rna.tf32.f32 %0, %1;" : "=f"(r) : "f"(x)); return r;
}

__device__ __forceinline__ void mma_tf32_16n8k8(
    float& d0, float& d1, float& d2, float& d3,
    uint32_t a0, uint32_t a1, uint32_t a2, uint32_t a3,
    uint32_t b0, uint32_t b1)
{
    asm volatile(
        "mma.sync.aligned.m16n8k8.row.col.f32.tf32.tf32.f32 "
        "{%0,%1,%2,%3}, {%4,%5,%6,%7}, {%8,%9}, {%0,%1,%2,%3};"
        : "+f"(d0), "+f"(d1), "+f"(d2), "+f"(d3)
        : "r"(a0), "r"(a1), "r"(a2), "r"(a3), "r"(b0), "r"(b1));
}

__device__ __forceinline__ void cp_async16(uint32_t s, const void* g) {
    asm volatile("cp.async.cg.shared.global [%0], [%1], 16;" :: "r"(s), "l"(g));
}
__device__ __forceinline__ void cp_commit() { asm volatile("cp.async.commit_group;" ::: "memory"); }
__device__ __forceinline__ void cp_wait0()  { asm volatile("cp.async.wait_group 0;" ::: "memory"); }
__device__ __forceinline__ void cp_wait1()  { asm volatile("cp.async.wait_group 1;" ::: "memory"); }

// ---------------- weight rounding pre-pass ----------------
__global__ void round_w(const float* __restrict__ s, float* __restrict__ d, int n4)
{
    int i = blockIdx.x * blockDim.x + threadIdx.x;
    if (i < n4) {
        float4 v = *(const float4*)&s[i * 4];
        v.x = to_tf32(v.x); v.y = to_tf32(v.y); v.z = to_tf32(v.z); v.w = to_tf32(v.w);
        *(float4*)&d[i * 4] = v;
    }
}

// ---------------- LayerNorm (tf32-rounded output) ----------------
__global__ __launch_bounds__(256) void ln_kernel(
    const float* __restrict__ x, const float* __restrict__ gam,
    const float* __restrict__ bet, float* __restrict__ out)
{
    __shared__ float red[20];
    int row = blockIdx.x;
    int tid = threadIdx.x;
    const float* xr = x + (size_t)row * D_;
    float4 v = *(const float4*)&xr[tid * 4];
    float s  = v.x + v.y + v.z + v.w;
    float sq = v.x * v.x + v.y * v.y + v.z * v.z + v.w * v.w;
    #pragma unroll
    for (int o = 16; o; o >>= 1) {
        s  += __shfl_xor_sync(0xffffffffu, s,  o);
        sq += __shfl_xor_sync(0xffffffffu, sq, o);
    }
    if ((tid & 31) == 0) { red[tid >> 5] = s; red[8 + (tid >> 5)] = sq; }
    __syncthreads();
    if (tid < 32) {
        float a = (tid < 8) ? red[tid]     : 0.f;
        float b = (tid < 8) ? red[8 + tid] : 0.f;
        #pragma unroll
        for (int o = 4; o; o >>= 1) {
            a += __shfl_xor_sync(0xffffffffu, a, o);
            b += __shfl_xor_sync(0xffffffffu, b, o);
        }
        if (tid == 0) { red[16] = a; red[17] = b; }
    }
    __syncthreads();
    float mean = red[16] * (1.f / D_);
    float var  = red[17] * (1.f / D_) - mean * mean;
    float rs   = rsqrtf(var + 1e-5f);
    float4 gv = *(const float4*)&gam[tid * 4];
    float4 bv = *(const float4*)&bet[tid * 4];
    float4 ov;
    ov.x = to_tf32((v.x - mean) * rs * gv.x + bv.x);
    ov.y = to_tf32((v.y - mean) * rs * gv.y + bv.y);
    ov.z = to_tf32((v.z - mean) * rs * gv.z + bv.z);
    ov.w = to_tf32((v.w - mean) * rs * gv.w + bv.w);
    *(float4*)&out[(size_t)row * D_ + tid * 4] = ov;
}

// ---------------- RoPE (rounds output to tf32) ----------------
__global__ void rope_kernel(float* __restrict__ buf, int nheads)
{
    int t = blockIdx.x;
    int h = blockIdx.y;
    int j = threadIdx.x;
    int s = t & (S_ - 1);
    float inv = exp2f(-(float)j * (13.287712379549449f / 32.0f));
    float ang = (float)s * inv;
    float sn, c;
    sincosf(ang, &sn, &c);
    float* p = buf + (size_t)t * (nheads * HD_) + h * HD_;
    float x1 = p[j], x2 = p[j + 32];
    p[j]      = to_tf32(x1 * c - x2 * sn);
    p[j + 32] = to_tf32(x1 * sn + x2 * c);
}

// ---------------- cp.async 3-stage tf32 GEMM -----------------------------
#define TBM 128
#define TBN 128
#define TBK 32
#define ASTR 36
#define BSTR 136
#define ASZ (TBM * ASTR)
#define BSZ (TBK * BSTR)
#define STG (ASZ + BSZ)
#define GEMM_SMEM (3 * STG * 4)    // 107520 B

enum { EPI_NONE = 0, EPI_RES = 1, EPI_BIAS_GELU = 2, EPI_BIAS_RES = 3, EPI_ROUND = 4 };

template <int EPI>
__device__ __forceinline__ void gemm_body(
    const float* __restrict__ A, const float* __restrict__ Bm,
    const float* __restrict__ bias, const float* __restrict__ res,
    float* __restrict__ C, int M, int N, int K, int m0, int n0, float* sm)
{
    int tid = threadIdx.x;
    int wid = tid >> 5, lane = tid & 31;
    int g = lane >> 2, tg = lane & 3;
    int wm = (wid & 3) * 32, wn = (wid >> 2) * 64;
    uint32_t smb = (uint32_t)__cvta_generic_to_shared(sm);

    auto issue = [&](int kc, int st) {
        int k0 = kc * TBK;
        uint32_t ab = smb + (uint32_t)(st * STG) * 4u;
        uint32_t bb = ab + ASZ * 4u;
        #pragma unroll
        for (int t = 0; t < 4; t++) {
            int i = tid + 256 * t;
            int mm = i >> 3, kq = i & 7;
            cp_async16(ab + (uint32_t)(mm * ASTR + kq * 4) * 4u,
                       &A[(size_t)(m0 + mm) * K + k0 + kq * 4]);
            int kk = i >> 5, nq = i & 31;
            cp_async16(bb + (uint32_t)(kk * BSTR + nq * 4) * 4u,
                       &Bm[(size_t)(k0 + kk) * N + n0 + nq * 4]);
        }
        cp_commit();
    };

    float c[2][8][4];
    #pragma unroll
    for (int mi = 0; mi < 2; mi++)
        #pragma unroll
        for (int ni = 0; ni < 8; ni++)
            #pragma unroll
            for (int e = 0; e < 4; e++) c[mi][ni][e] = 0.f;

    int nch = K / TBK;
    issue(0, 0);
    issue(1, 1);

    for (int cc = 0; cc < nch; cc++) {
        if (cc + 1 < nch) cp_wait1(); else cp_wait0();
        __syncthreads();
        if (cc + 2 < nch) issue(cc + 2, (cc + 2) % 3);
        float* As = sm + (cc % 3) * STG;
        float* Bs = As + ASZ;
        #pragma unroll
        for (int ks = 0; ks < 4; ks++) {
            int k0 = ks * 8;
            uint32_t a[2][4], b[8][2];
            #pragma unroll
            for (int mi = 0; mi < 2; mi++) {
                int rb = wm + mi * 16;
                a[mi][0] = __float_as_uint(As[(rb + g)     * ASTR + k0 + tg]);
                a[mi][1] = __float_as_uint(As[(rb + g + 8) * ASTR + k0 + tg]);
                a[mi][2] = __float_as_uint(As[(rb + g)     * ASTR + k0 + tg + 4]);
                a[mi][3] = __float_as_uint(As[(rb + g + 8) * ASTR + k0 + tg + 4]);
            }
            #pragma unroll
            for (int ni = 0; ni < 8; ni++) {
                int col = wn + ni * 8 + g;
                b[ni][0] = __float_as_uint(Bs[(k0 + tg)     * BSTR + col]);
                b[ni][1] = __float_as_uint(Bs[(k0 + tg + 4) * BSTR + col]);
            }
            #pragma unroll
            for (int mi = 0; mi < 2; mi++)
                #pragma unroll
                for (int ni = 0; ni < 8; ni++)
                    mma_tf32_16n8k8(c[mi][ni][0], c[mi][ni][1], c[mi][ni][2], c[mi][ni][3],
                                    a[mi][0], a[mi][1], a[mi][2], a[mi][3],
                                    b[ni][0], b[ni][1]);
        }
        __syncthreads();
    }

    #pragma unroll
    for (int mi = 0; mi < 2; mi++) {
        #pragma unroll
        for (int ni = 0; ni < 8; ni++) {
            int ccol = n0 + wn + ni * 8 + 2 * tg;
            #pragma unroll
            for (int hr = 0; hr < 2; hr++) {
                int r = m0 + wm + mi * 16 + g + hr * 8;
                float v0 = c[mi][ni][hr * 2 + 0];
                float v1 = c[mi][ni][hr * 2 + 1];
                size_t idx = (size_t)r * N + ccol;
                if (EPI == EPI_RES) { v0 += res[idx]; v1 += res[idx + 1]; }
                if (EPI == EPI_BIAS_GELU) {
                    float u0 = v0 + bias[ccol], u1 = v1 + bias[ccol + 1];
                    float z0 = 1.5957691216057308f * (u0 + 0.044715f * u0 * u0 * u0);
                    float z1 = 1.5957691216057308f * (u1 + 0.044715f * u1 * u1 * u1);
                    v0 = to_tf32(__fdividef(u0, 1.f + __expf(-z0)));
                    v1 = to_tf32(__fdividef(u1, 1.f + __expf(-z1)));
                }
                if (EPI == EPI_BIAS_RES) {
                    v0 += bias[ccol]     + res[idx];
                    v1 += bias[ccol + 1] + res[idx + 1];
                }
                if (EPI == EPI_ROUND) { v0 = to_tf32(v0); v1 = to_tf32(v1); }
                *(float2*)&C[idx] = make_float2(v0, v1);
            }
        }
    }
}

template <int EPI>
__global__ __launch_bounds__(256) void gemm_mma(
    const float* __restrict__ A, const float* __restrict__ Bm,
    const float* __restrict__ bias, const float* __restrict__ res,
    float* __restrict__ C, int M, int N, int K)
{
    extern __shared__ float sm[];
    gemm_body<EPI>(A, Bm, bias, res, C, M, N, K,
                   blockIdx.y * TBM, blockIdx.x * TBN, sm);
}

// fused QKV: grid (12, 32). bx<8 -> wq, bx 8-9 -> wk, bx 10-11 -> wv.
__global__ __launch_bounds__(256) void qkv_gemm(
    const float* __restrict__ h,
    const float* __restrict__ wq, const float* __restrict__ wk, const float* __restrict__ wv,
    float* __restrict__ q, float* __restrict__ k, float* __restrict__ v)
{
    extern __shared__ float sm[];
    int bx = blockIdx.x;
    const float* Bm; float* C; int N, n0;
    if (bx < 8)       { Bm = wq; C = q; N = D_;   n0 = bx * 128; }
    else if (bx < 10) { Bm = wk; C = k; N = KVD_; n0 = (bx - 8) * 128; }
    else              { Bm = wv; C = v; N = KVD_; n0 = (bx - 10) * 128; }
    gemm_body<EPI_ROUND>(h, Bm, nullptr, nullptr, C, M_, N, D_,
                         blockIdx.y * TBM, n0, sm);
}

// ---------------- tensor-core causal flash attention --------------------
// Paired q-tiles (bx & 15-bx) for uniform work; cp.async double-buffered K/V.
#define AQB 128
#define ACB 64
#define KVS 68
#define KVSTG (2 * ACB * KVS)                          // floats per stage (K+V)
#define ATTN_SMEM ((2 * KVSTG + 8 * 16 * KVS) * 4)     // 104448 B

__global__ __launch_bounds__(256) void attn_tc(
    const float* __restrict__ Q, const float* __restrict__ Kg,
    const float* __restrict__ Vg, float* __restrict__ O)
{
    extern __shared__ float sm[];
    float* Ps = sm + 2 * KVSTG;

    int tid = threadIdx.x, w = tid >> 5, lane = tid & 31;
    int g = lane >> 2, tg = lane & 3;
    int bx = blockIdx.x, hq = blockIdx.y, b = blockIdx.z;
    int kvh = hq & (HKV_ - 1);
    float* Pw = Ps + w * 16 * KVS;
    uint32_t smb = (uint32_t)__cvta_generic_to_shared(sm);

    int qts[2] = {15 - bx, bx};
    int nts[2] = {2 * (15 - bx) + 2, 2 * bx + 2};
    int total = nts[0] + nts[1];

    auto issue_kv = [&](int i, int st) {
        int kvt = (i < nts[0]) ? i : i - nts[0];
        int kv0 = kvt * ACB;
        uint32_t base = smb + (uint32_t)(st * KVSTG) * 4u;
        #pragma unroll
        for (int t = 0; t < 4; t++) {
            int s = tid + 256 * t;
            int kv = s >> 4, hd4 = (s & 15) * 4;
            size_t gidx = ((size_t)(b * S_ + kv0 + kv)) * KVD_ + kvh * HD_ + hd4;
            cp_async16(base + (uint32_t)(kv * KVS + hd4) * 4u, &Kg[gidx]);
            cp_async16(base + (uint32_t)((ACB + kv) * KVS + hd4) * 4u, &Vg[gidx]);
        }
        cp_commit();
    };

    uint32_t qf[8][4];
    float oc[8][4];
    float m0r, m1r, l0, l1;
    int q0 = qts[0] * AQB;
    int wrow = q0 + w * 16;

    auto load_q = [&]() {
        const float* Qb = Q + ((size_t)(b * S_ + wrow)) * D_ + hq * HD_;
        #pragma unroll
        for (int ks = 0; ks < 8; ks++) {
            qf[ks][0] = __float_as_uint(Qb[(size_t)g       * D_ + ks * 8 + tg]);
            qf[ks][1] = __float_as_uint(Qb[(size_t)(g + 8) * D_ + ks * 8 + tg]);
            qf[ks][2] = __float_as_uint(Qb[(size_t)g       * D_ + ks * 8 + tg + 4]);
            qf[ks][3] = __float_as_uint(Qb[(size_t)(g + 8) * D_ + ks * 8 + tg + 4]);
        }
    };
    auto reset_acc = [&]() {
        #pragma unroll
        for (int ni = 0; ni < 8; ni++)
            #pragma unroll
            for (int e = 0; e < 4; e++) oc[ni][e] = 0.f;
        m0r = -1e30f; m1r = -1e30f; l0 = 0.f; l1 = 0.f;
    };
    auto epilogue = [&]() {
        float il0 = 1.f / l0, il1 = 1.f / l1;
        size_t ob0 = ((size_t)(b * S_ + wrow + g))     * D_ + hq * HD_;
        size_t ob1 = ((size_t)(b * S_ + wrow + g + 8)) * D_ + hq * HD_;
        #pragma unroll
        for (int ni = 0; ni < 8; ni++) {
            int cc = ni * 8 + 2 * tg;
            *(float2*)&O[ob0 + cc] = make_float2(to_tf32(oc[ni][0] * il0), to_tf32(oc[ni][1] * il0));
            *(float2*)&O[ob1 + cc] = make_float2(to_tf32(oc[ni][2] * il1), to_tf32(oc[ni][3] * il1));
        }
    };

    load_q();
    reset_acc();
    issue_kv(0, 0);

    for (int i = 0; i < total; i++) {
        if (i + 1 < total) issue_kv(i + 1, (i + 1) & 1);
        if (i + 1 < total) cp_wait1(); else cp_wait0();
        __syncthreads();

        int kvt = (i < nts[0]) ? i : i - nts[0];
        int kv0 = kvt * ACB;
        float* Ks = sm + (i & 1) * KVSTG;
        float* Vs = Ks + ACB * KVS;

        bool active = (kv0 <= wrow + 15);
        if (active) {
            float sc[8][4];
            #pragma unroll
            for (int ni = 0; ni < 8; ni++)
                #pragma unroll
                for (int e = 0; e < 4; e++) sc[ni][e] = 0.f;
            #pragma unroll
            for (int ks = 0; ks < 8; ks++) {
                #pragma unroll
                for (int ni = 0; ni < 8; ni++) {
                    uint32_t b0 = __float_as_uint(Ks[(ni * 8 + g) * KVS + ks * 8 + tg]);
                    uint32_t b1 = __float_as_uint(Ks[(ni * 8 + g) * KVS + ks * 8 + tg + 4]);
                    mma_tf32_16n8k8(sc[ni][0], sc[ni][1], sc[ni][2], sc[ni][3],
                                    qf[ks][0], qf[ks][1], qf[ks][2], qf[ks][3], b0, b1);
                }
            }
            bool diag = (kv0 + ACB > wrow);
            int r0 = wrow + g, r1 = wrow + g + 8;
            #pragma unroll
            for (int ni = 0; ni < 8; ni++) {
                int c0 = kv0 + ni * 8 + 2 * tg, c1 = c0 + 1;
                sc[ni][0] *= 0.125f; sc[ni][1] *= 0.125f;
                sc[ni][2] *= 0.125f; sc[ni][3] *= 0.125f;
                if (diag) {
                    if (c0 > r0) sc[ni][0] = -1e9f;
                    if (c1 > r0) sc[ni][1] = -1e9f;
                    if (c0 > r1) sc[ni][2] = -1e9f;
                    if (c1 > r1) sc[ni][3] = -1e9f;
                }
            }
            float tm0 = -1e30f, tm1 = -1e30f;
            #pragma unroll
            for (int ni = 0; ni < 8; ni++) {
                tm0 = fmaxf(tm0, fmaxf(sc[ni][0], sc[ni][1]));
                tm1 = fmaxf(tm1, fmaxf(sc[ni][2], sc[ni][3]));
            }
            #pragma unroll
            for (int o = 1; o <= 2; o <<= 1) {
                tm0 = fmaxf(tm0, __shfl_xor_sync(0xffffffffu, tm0, o));
                tm1 = fmaxf(tm1, __shfl_xor_sync(0xffffffffu, tm1, o));
            }
            float mn0 = fmaxf(m0r, tm0), mn1 = fmaxf(m1r, tm1);
            float corr0 = __expf(m0r - mn0), corr1 = __expf(m1r - mn1);
            float ps0 = 0.f, ps1 = 0.f;
            #pragma unroll
            for (int ni = 0; ni < 8; ni++) {
                float p0 = __expf(sc[ni][0] - mn0);
                float p1 = __expf(sc[ni][1] - mn0);
                float p2 = __expf(sc[ni][2] - mn1);
                float p3 = __expf(sc[ni][3] - mn1);
                ps0 += p0 + p1; ps1 += p2 + p3;
                int cc = ni * 8 + 2 * tg;
                *(float2*)&Pw[g * KVS + cc]       = make_float2(to_tf32(p0), to_tf32(p1));
                *(float2*)&Pw[(g + 8) * KVS + cc] = make_float2(to_tf32(p2), to_tf32(p3));
            }
            #pragma unroll
            for (int o = 1; o <= 2; o <<= 1) {
                ps0 += __shfl_xor_sync(0xffffffffu, ps0, o);
                ps1 += __shfl_xor_sync(0xffffffffu, ps1, o);
            }
            l0 = l0 * corr0 + ps0; l1 = l1 * corr1 + ps1;
            m0r = mn0; m1r = mn1;
            #pragma unroll
            for (int ni = 0; ni < 8; ni++) {
                oc[ni][0] *= corr0; oc[ni][1] *= corr0;
                oc[ni][2] *= corr1; oc[ni][3] *= corr1;
            }
            __syncwarp();
            #pragma unroll
            for (int ks = 0; ks < 8; ks++) {
                uint32_t a0 = __float_as_uint(Pw[g       * KVS + ks * 8 + tg]);
                uint32_t a1 = __float_as_uint(Pw[(g + 8) * KVS + ks * 8 + tg]);
                uint32_t a2 = __float_as_uint(Pw[g       * KVS + ks * 8 + tg + 4]);
                uint32_t a3 = __float_as_uint(Pw[(g + 8) * KVS + ks * 8 + tg + 4]);
                #pragma unroll
                for (int ni = 0; ni < 8; ni++) {
                    uint32_t b0 = __float_as_uint(Vs[(ks * 8 + tg)     * KVS + ni * 8 + g]);
                    uint32_t b1 = __float_as_uint(Vs[(ks * 8 + tg + 4) * KVS + ni * 8 + g]);
                    mma_tf32_16n8k8(oc[ni][0], oc[ni][1], oc[ni][2], oc[ni][3],
                                    a0, a1, a2, a3, b0, b1);
                }
            }
        }
        __syncthreads();

        if (i == nts[0] - 1) {
            epilogue();
            q0 = qts[1] * AQB;
            wrow = q0 + w * 16;
            load_q();
            reset_acc();
        } else if (i == total - 1) {
            epilogue();
        }
    }
}

// ---------------- launch ----------------
extern "C" void kernel_launch(void* const* d_in, const int* in_sizes, int n_in,
                              void* d_out, int out_size)
{
    const float* x    = (const float*)d_in[0];
    const float* wq   = (const float*)d_in[2];
    const float* wk   = (const float*)d_in[3];
    const float* wv   = (const float*)d_in[4];
    const float* wo   = (const float*)d_in[5];
    const float* ln1g = (const float*)d_in[6];
    const float* ln1b = (const float*)d_in[7];
    const float* ln2g = (const float*)d_in[8];
    const float* ln2b = (const float*)d_in[9];
    const float* w1   = (const float*)d_in[10];
    const float* b1   = (const float*)d_in[11];
    const float* w2   = (const float*)d_in[12];
    const float* b2   = (const float*)d_in[13];
    float* out = (float*)d_out;

    float *h, *q, *k, *v, *o, *x2, *mid;
    float *rwq, *rwk, *rwv, *rwo, *rw1, *rw2;
    cudaGetSymbolAddress((void**)&h,   g_h);
    cudaGetSymbolAddress((void**)&q,   g_q);
    cudaGetSymbolAddress((void**)&k,   g_k);
    cudaGetSymbolAddress((void**)&v,   g_v);
    cudaGetSymbolAddress((void**)&o,   g_o);
    cudaGetSymbolAddress((void**)&x2,  g_x2);
    cudaGetSymbolAddress((void**)&mid, g_mid);
    cudaGetSymbolAddress((void**)&rwq, g_wq);
    cudaGetSymbolAddress((void**)&rwk, g_wk);
    cudaGetSymbolAddress((void**)&rwv, g_wv);
    cudaGetSymbolAddress((void**)&rwo, g_wo);
    cudaGetSymbolAddress((void**)&rw1, g_w1);
    cudaGetSymbolAddress((void**)&rw2, g_w2);

    cudaFuncSetAttribute(attn_tc,  cudaFuncAttributeMaxDynamicSharedMemorySize, ATTN_SMEM);
    cudaFuncSetAttribute(qkv_gemm, cudaFuncAttributeMaxDynamicSharedMemorySize, GEMM_SMEM);
    cudaFuncSetAttribute(gemm_mma<EPI_RES>,       cudaFuncAttributeMaxDynamicSharedMemorySize, GEMM_SMEM);
    cudaFuncSetAttribute(gemm_mma<EPI_BIAS_GELU>, cudaFuncAttributeMaxDynamicSharedMemorySize, GEMM_SMEM);
    cudaFuncSetAttribute(gemm_mma<EPI_BIAS_RES>,  cudaFuncAttributeMaxDynamicSharedMemorySize, GEMM_SMEM);

    // 0. round weights to tf32 (scratch)
    round_w<<<(D_ * D_ / 4 + 255) / 256, 256>>>(wq, rwq, D_ * D_ / 4);
    round_w<<<(D_ * KVD_ / 4 + 255) / 256, 256>>>(wk, rwk, D_ * KVD_ / 4);
    round_w<<<(D_ * KVD_ / 4 + 255) / 256, 256>>>(wv, rwv, D_ * KVD_ / 4);
    round_w<<<(D_ * D_ / 4 + 255) / 256, 256>>>(wo, rwo, D_ * D_ / 4);
    round_w<<<(D_ * P_ / 4 + 255) / 256, 256>>>(w1, rw1, D_ * P_ / 4);
    round_w<<<(P_ * D_ / 4 + 255) / 256, 256>>>(w2, rw2, P_ * D_ / 4);

    // 1. h = LN1(x)  (tf32-rounded)
    ln_kernel<<<M_, 256>>>(x, ln1g, ln1b, h);
    // 2. fused q/k/v projection (outputs tf32-rounded)
    qkv_gemm<<<dim3(12, M_ / TBM), 256, GEMM_SMEM>>>(h, rwq, rwk, rwv, q, k, v);
    // 3-4. RoPE (outputs tf32-rounded)
    rope_kernel<<<dim3(M_, HQ_),  32>>>(q, HQ_);
    rope_kernel<<<dim3(M_, HKV_), 32>>>(k, HKV_);
    // 5. attention (paired q-tiles, cp.async K/V)
    attn_tc<<<dim3(8, HQ_, B_), 256, ATTN_SMEM>>>(q, k, v, o);
    // 6. x2 = x + o @ wo
    gemm_mma<EPI_RES><<<dim3(D_ / TBN, M_ / TBM), 256, GEMM_SMEM>>>(o, rwo, nullptr, x, x2, M_, D_, D_);
    // 7. h2 = LN2(x2)
    ln_kernel<<<M_, 256>>>(x2, ln2g, ln2b, h);
    // 8. mid = gelu(h2 @ w1 + b1)  (tf32-rounded)
    gemm_mma<EPI_BIAS_GELU><<<dim3(P_ / TBN, M_ / TBM), 256, GEMM_SMEM>>>(h, rw1, b1, nullptr, mid, M_, P_, D_);
    // 9. out = x2 + mid @ w2 + b2
    gemm_mma<EPI_BIAS_RES><<<dim3(D_ / TBN, M_ / TBM), 256, GEMM_SMEM>>>(mid, rw2, b2, x2, out, M_, D_, P_);
}